// round 1
// baseline (speedup 1.0000x reference)
#include <cuda_runtime.h>
#include <math.h>

// Problem constants
#define TT  512
#define BBATCH 128
#define DD  512
#define HHID 64
#define NROWS (TT * BBATCH)      // 65536 independent (t,b) rows
#define NGATE 192                // 3 used gates (input, update, output) x 64 qubits
#define EPSV 1e-5f

// Scratch (allocation-free: device globals)
__device__ float g_h0[NROWS * HHID];        // layer-0 layernormed output, 16 MB
__device__ float g_WT0[DD * NGATE];         // W0 gates 1..3, transposed to [K][N]
__device__ float g_WT1[HHID * NGATE];       // W1 gates 1..3, transposed to [K][N]

// ---------------------------------------------------------------------------
// Prolog: transpose weights to K-major so the GEMM reads them coalesced.
// W is [4, NQ, Din+H] row-major; we keep gates 1..3 and columns 0..K-1 only
// (concat tail multiplies zeros; forget gate multiplies c_prev == 0).
// ---------------------------------------------------------------------------
__global__ void transpose_w_kernel(const float* __restrict__ W0,
                                   const float* __restrict__ W1) {
    int idx = blockIdx.x * blockDim.x + threadIdx.x;
    if (idx < DD * NGATE) {
        int k = idx / NGATE, n = idx % NGATE;
        g_WT0[idx] = W0[(size_t)(64 + n) * (DD + HHID) + k];
    }
    if (idx < HHID * NGATE) {
        int k = idx / NGATE, n = idx % NGATE;
        g_WT1[idx] = W1[(size_t)(64 + n) * (HHID + HHID) + k];
    }
}

__device__ __forceinline__ float sigmoidf_(float x) {
    return 1.0f / (1.0f + expf(-x));
}

// ---------------------------------------------------------------------------
// Fused layer kernel: z = x @ W^T  (M=65536, N=192, K=512 or 64), then per row:
//   q = cumprod(cos(z + b + th)) over 64 qubits per gate (warp shuffle scan),
//   i = sig(q1); g = tanh(sig(q2)); o = sig(q3); c = i*g; h = o*tanh(c);
//   layernorm over H=64 (warp reductions); write h_ln (+ last-timestep h,c).
// Block tile: BM=32 rows x BN=192 (full gate width so epilogue is block-local).
// ---------------------------------------------------------------------------
template <int K>
__global__ __launch_bounds__(256)
void qlstm_layer_kernel(const float* __restrict__ x,      // [NROWS, K]
                        const float* __restrict__ WT,     // [K, 192]
                        const float* __restrict__ bvec,   // [4*64]
                        const float* __restrict__ thvec,  // [4*64]
                        const float* __restrict__ gamma,  // [64]
                        const float* __restrict__ beta,   // [64]
                        float* __restrict__ hln_out,      // [NROWS, 64]
                        float* __restrict__ hlast,        // [128, 64]
                        float* __restrict__ clast)        // [128, 64]
{
    constexpr int BM = 32, BN = NGATE, BK = 16;

    __shared__ float xs[BK][BM];                 // 2 KB   (K-major x tile)
    __shared__ __align__(16) float ws[BK][BN];   // 12 KB
    __shared__ float zs[BM][BN];                 // 24 KB
    __shared__ float bt[BN];                     // b + th fused
    __shared__ float gmm[HHID], bet[HHID];

    const int tid  = threadIdx.x;
    const int row0 = blockIdx.x * BM;

    if (tid < NGATE) bt[tid] = bvec[64 + tid] + thvec[64 + tid];
    if (tid < HHID)  { gmm[tid] = gamma[tid]; bet[tid] = beta[tid]; }

    const int tc = tid & 15;       // col group: columns tc*12 .. tc*12+11
    const int tr = tid >> 4;       // row group: rows 2*tr, 2*tr+1

    float acc[2][12];
#pragma unroll
    for (int i = 0; i < 2; i++)
#pragma unroll
        for (int j = 0; j < 12; j++) acc[i][j] = 0.0f;

    for (int kt = 0; kt < K; kt += BK) {
        __syncthreads();
        // x tile: 32 rows x 16 k, transposed into xs[k][m]
        if (tid < 128) {
            int r = tid >> 2, s = tid & 3;
            float4 v = *(const float4*)(x + (size_t)(row0 + r) * K + kt + s * 4);
            xs[s * 4 + 0][r] = v.x;
            xs[s * 4 + 1][r] = v.y;
            xs[s * 4 + 2][r] = v.z;
            xs[s * 4 + 3][r] = v.w;
        }
        // W tile: 16 k x 192 n, coalesced float4 loads
#pragma unroll
        for (int i = 0; i < 3; i++) {
            int f = tid + i * 256;          // 0..767 float4s
            int k = f / 48, n4 = f % 48;
            float4 v = *(const float4*)(WT + (size_t)(kt + k) * BN + n4 * 4);
            *(float4*)&ws[k][n4 * 4] = v;
        }
        __syncthreads();

#pragma unroll
        for (int k = 0; k < BK; k++) {
            float a0 = xs[k][2 * tr];
            float a1 = xs[k][2 * tr + 1];
            float bv[12];
#pragma unroll
            for (int j = 0; j < 3; j++) {
                float4 w4 = *(const float4*)&ws[k][tc * 12 + j * 4];
                bv[j * 4 + 0] = w4.x; bv[j * 4 + 1] = w4.y;
                bv[j * 4 + 2] = w4.z; bv[j * 4 + 3] = w4.w;
            }
#pragma unroll
            for (int j = 0; j < 12; j++) {
                acc[0][j] = fmaf(a0, bv[j], acc[0][j]);
                acc[1][j] = fmaf(a1, bv[j], acc[1][j]);
            }
        }
    }

    __syncthreads();
#pragma unroll
    for (int i = 0; i < 2; i++)
#pragma unroll
        for (int j = 0; j < 12; j++)
            zs[2 * tr + i][tc * 12 + j] = acc[i][j];
    __syncthreads();

    // ---------------- epilogue: warp per row, 4 rows per warp ----------------
    const int warp = tid >> 5, lane = tid & 31;
    const int n0 = 2 * lane, n1 = 2 * lane + 1;

#pragma unroll
    for (int rr = 0; rr < 4; rr++) {
        int r    = warp * 4 + rr;
        int grow = row0 + r;

        float sg[3][2];   // sigmoid(q) per gate per local qubit
#pragma unroll
        for (int g = 0; g < 3; g++) {
            float z0 = zs[r][g * 64 + n0] + bt[g * 64 + n0];
            float z1 = zs[r][g * 64 + n1] + bt[g * 64 + n1];
            float c0 = cosf(z0);
            float c1 = cosf(z1);
            float incl = c0 * c1;
            // inclusive multiply-scan across lanes (pairs of qubits)
#pragma unroll
            for (int off = 1; off < 32; off <<= 1) {
                float t = __shfl_up_sync(0xffffffffu, incl, off);
                if (lane >= off) incl *= t;
            }
            float excl = __shfl_up_sync(0xffffffffu, incl, 1);
            if (lane == 0) excl = 1.0f;
            float q0 = excl * c0;   // cumprod up to qubit 2*lane
            float q1 = incl;        // cumprod up to qubit 2*lane+1
            sg[g][0] = sigmoidf_(q0);
            sg[g][1] = sigmoidf_(q1);
        }
        // c = i * tanh(sigmoid(update)); h = o * tanh(c)
        float cv0 = sg[0][0] * tanhf(sg[1][0]);
        float cv1 = sg[0][1] * tanhf(sg[1][1]);
        float h0v = sg[2][0] * tanhf(cv0);
        float h1v = sg[2][1] * tanhf(cv1);

        // layernorm over 64 values held 2-per-lane
        float s = h0v + h1v;
#pragma unroll
        for (int off = 16; off; off >>= 1) s += __shfl_xor_sync(0xffffffffu, s, off);
        float mu = s * (1.0f / 64.0f);
        float d0 = h0v - mu, d1 = h1v - mu;
        float ss = d0 * d0 + d1 * d1;
#pragma unroll
        for (int off = 16; off; off >>= 1) ss += __shfl_xor_sync(0xffffffffu, ss, off);
        float rinv = rsqrtf(ss * (1.0f / 64.0f) + EPSV);

        float o0 = d0 * rinv * gmm[n0] + bet[n0];
        float o1 = d1 * rinv * gmm[n1] + bet[n1];

        *(float2*)(hln_out + (size_t)grow * HHID + n0) = make_float2(o0, o1);

        if (grow >= NROWS - BBATCH) {          // t == T-1
            int bi = grow - (NROWS - BBATCH);
            *(float2*)(hlast + (size_t)bi * HHID + n0) = make_float2(o0, o1);
            *(float2*)(clast + (size_t)bi * HHID + n0) = make_float2(cv0, cv1);
        }
    }
}

// ---------------------------------------------------------------------------
// Launch: transpose prolog, then layer 0 (K=512), then layer 1 (K=64).
// Output tuple layout: [outputs 512*128*64][h0_last 128*64][c0_last 128*64]
//                      [h1_last 128*64][c1_last 128*64]
// ---------------------------------------------------------------------------
extern "C" void kernel_launch(void* const* d_in, const int* in_sizes, int n_in,
                              void* d_out, int out_size) {
    const float* inputs = (const float*)d_in[0];
    const float* W0  = (const float*)d_in[1];
    const float* b0  = (const float*)d_in[2];
    const float* th0 = (const float*)d_in[3];
    const float* g0  = (const float*)d_in[4];
    const float* be0 = (const float*)d_in[5];
    const float* W1  = (const float*)d_in[6];
    const float* b1  = (const float*)d_in[7];
    const float* th1 = (const float*)d_in[8];
    const float* g1  = (const float*)d_in[9];
    const float* be1 = (const float*)d_in[10];

    float* out = (float*)d_out;
    const size_t out_main = (size_t)NROWS * HHID;        // 4194304
    float* h0last = out + out_main;
    float* c0last = h0last + BBATCH * HHID;
    float* h1last = c0last + BBATCH * HHID;
    float* c1last = h1last + BBATCH * HHID;

    float *h0p, *wt0p, *wt1p;
    cudaGetSymbolAddress((void**)&h0p,  g_h0);
    cudaGetSymbolAddress((void**)&wt0p, g_WT0);
    cudaGetSymbolAddress((void**)&wt1p, g_WT1);

    transpose_w_kernel<<<(DD * NGATE + 255) / 256, 256>>>(W0, W1);

    qlstm_layer_kernel<DD><<<NROWS / 32, 256>>>(
        inputs, wt0p, b0, th0, g0, be0, h0p, h0last, c0last);

    qlstm_layer_kernel<HHID><<<NROWS / 32, 256>>>(
        h0p, wt1p, b1, th1, g1, be1, out, h1last, c1last);
}

// round 3
// speedup vs baseline: 3.9553x; 3.9553x over previous
#include <cuda_runtime.h>
#include <cuda_bf16.h>
#include <math.h>
#include <stdint.h>

// ---------------------------------------------------------------- constants
#define TT     512
#define BB     128
#define DDIM   512
#define HH     64
#define NROWS  (TT * BB)          // 65536 independent (t,b) rows
#define NG     192                // 3 gates (i, g, o) x 64 qubits
#define EPSV   1e-5f

// Arch-specific feature gate: tcgen05 exists only on sm_10xa targets.
#if defined(__CUDA_ARCH__) && (defined(__CUDA_ARCH_FEAT_SM103_ALL) || \
    defined(__CUDA_ARCH_FEAT_SM100_ALL) || defined(__CUDA_ARCH_SPECIFIC__))
#define HAS_TC 1
#endif

// dynamic SMEM layout for the tensor kernel (tile bases 1024-aligned)
#define OFF_A_HI   0              // 2 x 16384  (128 rows x 64 bf16)
#define OFF_A_LO   32768          // 2 x 16384
#define OFF_B_HI   65536          // 2 x 24576  (192 rows x 64 bf16)
#define OFF_B_LO   114688         // 2 x 24576
#define OFF_MISC   163840         // tmem ptr, mbarriers, bt/gamma/beta
#define SMEM_TOTAL 165888

// idesc: kind::f16, bf16 x bf16 -> f32, M=128, N=192
#define IDESC ((1u << 4) | (1u << 7) | (1u << 10) | ((NG / 8) << 17) | ((128 / 16) << 24))

// ---------------------------------------------------------------- scratch
__device__ float          g_h0[NROWS * HH];      // layer-0 output, 16 MB
__device__ __nv_bfloat16  g_B0hi[8 * NG * 64];   // W0: 8 K-chunks, SW128 swizzled
__device__ __nv_bfloat16  g_B0lo[8 * NG * 64];
__device__ __nv_bfloat16  g_B1hi[NG * 64];       // W1: 1 K-chunk
__device__ __nv_bfloat16  g_B1lo[NG * 64];
__device__ float          g_WT0[DDIM * NG];      // scalar path: W0 K-major
__device__ float          g_WT1[HH * NG];        // scalar path: W1 K-major

// ================================================================ prolog kernels
__global__ void transpose_w_kernel(const float* __restrict__ W0,
                                   const float* __restrict__ W1) {
    int idx = blockIdx.x * blockDim.x + threadIdx.x;
    if (idx < DDIM * NG) {
        int k = idx / NG, n = idx % NG;
        g_WT0[idx] = W0[(size_t)(64 + n) * (DDIM + HH) + k];
    }
    if (idx < HH * NG) {
        int k = idx / NG, n = idx % NG;
        g_WT1[idx] = W1[(size_t)(64 + n) * (HH + HH) + k];
    }
}

// Split W (gates 1..3, first K cols) into bf16 hi/lo, laid out as B-operand
// K-major SW128 tiles: per 64-K chunk, [192 rows x 128 B], 8-row atoms.
__global__ void prep_w_kernel(const float* __restrict__ W0,
                              const float* __restrict__ W1) {
    int idx = blockIdx.x * blockDim.x + threadIdx.x;
    if (idx < 8 * NG * 64) {
        int c   = idx / (NG * 64);
        int rem = idx % (NG * 64);
        int n   = rem / 64, kl = rem % 64;
        float w = W0[(size_t)(64 + n) * (DDIM + HH) + c * 64 + kl];
        __nv_bfloat16 hi = __float2bfloat16(w);
        __nv_bfloat16 lo = __float2bfloat16(w - __bfloat162float(hi));
        uint32_t boff = ((uint32_t)(n >> 3)) * 1024 + ((uint32_t)(n & 7)) * 128 + kl * 2;
        boff ^= ((boff >> 3) & 0x70);
        g_B0hi[(size_t)c * (NG * 64) + boff / 2] = hi;
        g_B0lo[(size_t)c * (NG * 64) + boff / 2] = lo;
    }
    if (idx < NG * 64) {
        int n = idx / 64, kl = idx % 64;
        float w = W1[(size_t)(64 + n) * (HH + HH) + kl];
        __nv_bfloat16 hi = __float2bfloat16(w);
        __nv_bfloat16 lo = __float2bfloat16(w - __bfloat162float(hi));
        uint32_t boff = ((uint32_t)(n >> 3)) * 1024 + ((uint32_t)(n & 7)) * 128 + kl * 2;
        boff ^= ((boff >> 3) & 0x70);
        g_B1hi[boff / 2] = hi;
        g_B1lo[boff / 2] = lo;
    }
}

// ================================================================ PTX helpers
#ifdef HAS_TC
static __device__ __forceinline__ uint32_t smem_u32(const void* p) {
    uint32_t a;
    asm("{ .reg .u64 t; cvta.to.shared.u64 t, %1; cvt.u32.u64 %0, t; }"
        : "=r"(a) : "l"(p));
    return a;
}
static __device__ __forceinline__ uint32_t elect1() {
    uint32_t p;
    asm volatile("{\n .reg .pred p;\n elect.sync _|p, 0xFFFFFFFF;\n selp.b32 %0,1,0,p;\n}"
                 : "=r"(p));
    return p;
}
static __device__ __forceinline__ uint64_t sdesc(uint32_t addr) {
    // SW128, Blackwell version=1, SBO=64 (1024B per 8-row group), LBO=1 (16B)
    return (2ull << 61) | (1ull << 46) | (64ull << 32) | (1ull << 16)
         | ((uint64_t)(addr >> 4) & 0x3FFF);
}
static __device__ __forceinline__ void mma_bf16_ss(uint32_t d, uint64_t ad, uint64_t bd,
                                                   uint32_t idesc, bool accum) {
    uint32_t en = accum ? 1u : 0u;
    asm volatile(
        "{\n\t"
        ".reg .pred p;\n\t"
        "setp.ne.u32 p, %5, 0;\n\t"
        "tcgen05.mma.cta_group::1.kind::f16 [%0], %1, %2, %3, {%4, %4, %4, %4}, p;\n\t"
        "}"
        :: "r"(d), "l"(ad), "l"(bd), "r"(idesc), "r"(0u), "r"(en)
        : "memory");
}
static __device__ __forceinline__ void mbar_wait(uint32_t mbar, uint32_t parity) {
    uint32_t done;
    asm volatile(
        "{\n .reg .pred p;\n"
        " mbarrier.try_wait.parity.acquire.cta.shared::cta.b64 p, [%1], %2;\n"
        " selp.b32 %0, 1, 0, p;\n}"
        : "=r"(done) : "r"(mbar), "r"(parity) : "memory");
    if (!done) {
        asm volatile(
            "{\n .reg .pred P1;\n"
            "WL%=:\n"
            " mbarrier.try_wait.parity.acquire.cta.shared::cta.b64 P1, [%0], %1, 0x989680;\n"
            " @P1 bra.uni WD%=;\n"
            " bra.uni WL%=;\n"
            "WD%=:\n}"
            :: "r"(mbar), "r"(parity) : "memory");
    }
}
#define TC_WAIT_LD() asm volatile("tcgen05.wait::ld.sync.aligned;" ::: "memory")
#define LDTM_X32(r, addr)                                              \
    asm volatile(                                                       \
        "tcgen05.ld.sync.aligned.32x32b.x32.b32 "                       \
        "{%0, %1, %2, %3, %4, %5, %6, %7, "                             \
        " %8, %9, %10, %11, %12, %13, %14, %15, "                       \
        " %16, %17, %18, %19, %20, %21, %22, %23, "                     \
        " %24, %25, %26, %27, %28, %29, %30, %31}, [%32];"              \
        : "=r"((r)[0]),  "=r"((r)[1]),  "=r"((r)[2]),  "=r"((r)[3]),    \
          "=r"((r)[4]),  "=r"((r)[5]),  "=r"((r)[6]),  "=r"((r)[7]),    \
          "=r"((r)[8]),  "=r"((r)[9]),  "=r"((r)[10]), "=r"((r)[11]),   \
          "=r"((r)[12]), "=r"((r)[13]), "=r"((r)[14]), "=r"((r)[15]),   \
          "=r"((r)[16]), "=r"((r)[17]), "=r"((r)[18]), "=r"((r)[19]),   \
          "=r"((r)[20]), "=r"((r)[21]), "=r"((r)[22]), "=r"((r)[23]),   \
          "=r"((r)[24]), "=r"((r)[25]), "=r"((r)[26]), "=r"((r)[27]),   \
          "=r"((r)[28]), "=r"((r)[29]), "=r"((r)[30]), "=r"((r)[31])    \
        : "r"(addr))
#endif // HAS_TC

// ================================================================ tensor kernel
// Per CTA: 128 rows x 192 gate cols. K in 64-chunks, double-buffered SMEM,
// tcgen05 bf16 3-term split GEMM (fp32 TMEM accum), fused in-thread epilogue.
// Compiles to an empty kernel on non-arch-specific targets.
template <int NC>
__global__ void __launch_bounds__(128, 1)
qlstm_tc_kernel(const float* __restrict__ x,
                const __nv_bfloat16* __restrict__ Bhi_g,
                const __nv_bfloat16* __restrict__ Blo_g,
                const float* __restrict__ bvec,
                const float* __restrict__ thvec,
                const float* __restrict__ gamma,
                const float* __restrict__ beta,
                float* __restrict__ hout,
                float* __restrict__ hlast,
                float* __restrict__ clast)
{
#ifdef HAS_TC
    constexpr int K = NC * 64;
    extern __shared__ __align__(1024) char smem[];
    const uint32_t sb = smem_u32(smem);
    const int tid = threadIdx.x, wid = tid >> 5, lane = tid & 31;
    const int row0 = blockIdx.x * 128;

    float* bt  = (float*)(smem + OFF_MISC + 32);
    float* gm  = bt + NG;
    float* bet = gm + HH;
    for (int i = tid; i < NG; i += 128) bt[i] = bvec[64 + i] + thvec[64 + i];
    if (tid < HH) { gm[tid] = gamma[tid]; bet[tid] = beta[tid]; }

    const uint32_t mb0 = sb + OFF_MISC + 8;
    if (wid == 0) {
        asm volatile("tcgen05.alloc.cta_group::1.sync.aligned.shared::cta.b32 [%0], %1;"
                     :: "r"(sb + OFF_MISC), "r"(256u) : "memory");
        asm volatile("tcgen05.relinquish_alloc_permit.cta_group::1.sync.aligned;");
    }
    if (tid == 0) {
        asm volatile("mbarrier.init.shared.b64 [%0], %1;" :: "r"(mb0),     "r"(1u) : "memory");
        asm volatile("mbarrier.init.shared.b64 [%0], %1;" :: "r"(mb0 + 8), "r"(1u) : "memory");
    }
    __syncthreads();
    uint32_t tmem;
    asm volatile("ld.shared.b32 %0, [%1];" : "=r"(tmem) : "r"(sb + OFF_MISC));

    // ---------------- K-chunk pipeline ----------------
    for (int c = 0; c < NC; c++) {
        const int b = c & 1;
        if (c >= 2) mbar_wait(mb0 + b * 8, ((c >> 1) - 1) & 1);

        {   // A chunk: fp32 -> bf16 hi/lo, SW128-swizzled STS
            char* ah = smem + OFF_A_HI + b * 16384;
            char* al = smem + OFF_A_LO + b * 16384;
#pragma unroll
            for (int j = 0; j < 16; j++) {
                int idx = tid + j * 128;
                int r = idx >> 4, s = idx & 15;
                float4 v = *(const float4*)(x + (size_t)(row0 + r) * K + c * 64 + s * 4);
                __nv_bfloat16 hx = __float2bfloat16(v.x);
                __nv_bfloat16 hy = __float2bfloat16(v.y);
                __nv_bfloat16 hz = __float2bfloat16(v.z);
                __nv_bfloat16 hw = __float2bfloat16(v.w);
                __nv_bfloat16 lx = __float2bfloat16(v.x - __bfloat162float(hx));
                __nv_bfloat16 ly = __float2bfloat16(v.y - __bfloat162float(hy));
                __nv_bfloat16 lz = __float2bfloat16(v.z - __bfloat162float(hz));
                __nv_bfloat16 lw = __float2bfloat16(v.w - __bfloat162float(hw));
                uint32_t off = (uint32_t)r * 128 + (uint32_t)s * 8;
                off ^= ((off >> 3) & 0x70);
                *(__nv_bfloat162*)(ah + off)     = __nv_bfloat162(hx, hy);
                *(__nv_bfloat162*)(ah + off + 4) = __nv_bfloat162(hz, hw);
                *(__nv_bfloat162*)(al + off)     = __nv_bfloat162(lx, ly);
                *(__nv_bfloat162*)(al + off + 4) = __nv_bfloat162(lz, lw);
            }
        }
        {   // B chunk: pre-swizzled, raw float4 copy
            const float4* bh = (const float4*)(Bhi_g + (size_t)c * (NG * 64));
            const float4* bl = (const float4*)(Blo_g + (size_t)c * (NG * 64));
            float4* sh = (float4*)(smem + OFF_B_HI + b * 24576);
            float4* sl = (float4*)(smem + OFF_B_LO + b * 24576);
#pragma unroll
            for (int j = 0; j < 12; j++) {
                int idx = tid + j * 128;
                sh[idx] = bh[idx];
                sl[idx] = bl[idx];
            }
        }
        __syncthreads();

        if (wid == 0 && elect1()) {
            asm volatile("fence.proxy.async.shared::cta;" ::: "memory");
            uint64_t aH = sdesc(sb + OFF_A_HI + b * 16384);
            uint64_t aL = sdesc(sb + OFF_A_LO + b * 16384);
            uint64_t bH = sdesc(sb + OFF_B_HI + b * 24576);
            uint64_t bL = sdesc(sb + OFF_B_LO + b * 24576);
#pragma unroll
            for (int ks = 0; ks < 4; ks++)
                mma_bf16_ss(tmem, aH + ks * 2, bH + ks * 2, IDESC, !(c == 0 && ks == 0));
#pragma unroll
            for (int ks = 0; ks < 4; ks++)
                mma_bf16_ss(tmem, aH + ks * 2, bL + ks * 2, IDESC, true);
#pragma unroll
            for (int ks = 0; ks < 4; ks++)
                mma_bf16_ss(tmem, aL + ks * 2, bH + ks * 2, IDESC, true);
            asm volatile(
                "tcgen05.commit.cta_group::1.mbarrier::arrive::one.shared::cluster.b64 [%0];"
                :: "r"(mb0 + b * 8) : "memory");
        }
    }

    mbar_wait(mb0 + ((NC - 1) & 1) * 8, ((NC - 1) >> 1) & 1);
    asm volatile("tcgen05.fence::after_thread_sync;" ::: "memory");

    // ---------------- epilogue: thread = TMEM lane = row ----------------
    const int myrow = row0 + wid * 32 + lane;
    float hv[64];
    uint32_t rg[32];

    {   // gate i: sigmoid(cumprod cos)
        float cum = 1.0f;
#pragma unroll
        for (int half = 0; half < 2; half++) {
            LDTM_X32(rg, tmem + half * 32);
            TC_WAIT_LD();
#pragma unroll
            for (int j = 0; j < 32; j++) {
                int col = half * 32 + j;
                float z = __uint_as_float(rg[j]) + bt[col];
                cum *= __cosf(z);
                hv[col] = 1.0f / (1.0f + __expf(-cum));
            }
        }
    }
    {   // gate g: c = i * tanh(sigmoid(cumprod cos))
        float cum = 1.0f;
#pragma unroll
        for (int half = 0; half < 2; half++) {
            LDTM_X32(rg, tmem + 64 + half * 32);
            TC_WAIT_LD();
#pragma unroll
            for (int j = 0; j < 32; j++) {
                int col = half * 32 + j;
                float z = __uint_as_float(rg[j]) + bt[64 + col];
                cum *= __cosf(z);
                float sg = 1.0f / (1.0f + __expf(-cum));
                hv[col] *= tanhf(sg);
            }
        }
    }
    const bool tail = (myrow >= NROWS - BB);
    if (tail) {
        float4* cd = (float4*)(clast + (size_t)(myrow - (NROWS - BB)) * HH);
#pragma unroll
        for (int j = 0; j < 16; j++)
            cd[j] = make_float4(hv[4*j], hv[4*j+1], hv[4*j+2], hv[4*j+3]);
    }
    {   // gate o: h = o * tanh(c)
        float cum = 1.0f;
#pragma unroll
        for (int half = 0; half < 2; half++) {
            LDTM_X32(rg, tmem + 128 + half * 32);
            TC_WAIT_LD();
#pragma unroll
            for (int j = 0; j < 32; j++) {
                int col = half * 32 + j;
                float z = __uint_as_float(rg[j]) + bt[128 + col];
                cum *= __cosf(z);
                float sg = 1.0f / (1.0f + __expf(-cum));
                hv[col] = sg * tanhf(hv[col]);
            }
        }
    }
    // layernorm over the 64 in-register values
    float s = 0.0f;
#pragma unroll
    for (int j = 0; j < 64; j++) s += hv[j];
    float mu = s * (1.0f / 64.0f);
    float ss = 0.0f;
#pragma unroll
    for (int j = 0; j < 64; j++) { float d = hv[j] - mu; ss += d * d; }
    float rinv = rsqrtf(ss * (1.0f / 64.0f) + EPSV);
#pragma unroll
    for (int j = 0; j < 64; j++) hv[j] = (hv[j] - mu) * rinv * gm[j] + bet[j];

    float4* od = (float4*)(hout + (size_t)myrow * HH);
#pragma unroll
    for (int j = 0; j < 16; j++)
        od[j] = make_float4(hv[4*j], hv[4*j+1], hv[4*j+2], hv[4*j+3]);
    if (tail) {
        float4* hd = (float4*)(hlast + (size_t)(myrow - (NROWS - BB)) * HH);
#pragma unroll
        for (int j = 0; j < 16; j++)
            hd[j] = make_float4(hv[4*j], hv[4*j+1], hv[4*j+2], hv[4*j+3]);
    }

    asm volatile("tcgen05.fence::before_thread_sync;" ::: "memory");
    __syncthreads();
    if (wid == 0) {
        asm volatile("tcgen05.dealloc.cta_group::1.sync.aligned.b32 %0, %1;"
                     :: "r"(tmem), "r"(256u));
    }
#endif // HAS_TC
}

// ================================================================ scalar kernel
// R1's proven FFMA kernel (1053us). Active only when tcgen05 is unavailable
// on the compiled target; otherwise compiles to an empty kernel.
__device__ __forceinline__ float sigmoidf_(float x) {
    return 1.0f / (1.0f + expf(-x));
}

template <int K>
__global__ __launch_bounds__(256)
void qlstm_layer_kernel(const float* __restrict__ x,
                        const float* __restrict__ WT,
                        const float* __restrict__ bvec,
                        const float* __restrict__ thvec,
                        const float* __restrict__ gamma,
                        const float* __restrict__ beta,
                        float* __restrict__ hln_out,
                        float* __restrict__ hlast,
                        float* __restrict__ clast)
{
#ifndef HAS_TC
    constexpr int BM = 32, BN = NG, BK = 16;
    __shared__ float xs[BK][BM];
    __shared__ __align__(16) float ws[BK][BN];
    __shared__ float zs[BM][BN];
    __shared__ float bt[BN];
    __shared__ float gmm[HH], bet[HH];

    const int tid  = threadIdx.x;
    const int row0 = blockIdx.x * BM;

    if (tid < NG) bt[tid] = bvec[64 + tid] + thvec[64 + tid];
    if (tid < HH) { gmm[tid] = gamma[tid]; bet[tid] = beta[tid]; }

    const int tc = tid & 15;
    const int tr = tid >> 4;

    float acc[2][12];
#pragma unroll
    for (int i = 0; i < 2; i++)
#pragma unroll
        for (int j = 0; j < 12; j++) acc[i][j] = 0.0f;

    for (int kt = 0; kt < K; kt += BK) {
        __syncthreads();
        if (tid < 128) {
            int r = tid >> 2, s = tid & 3;
            float4 v = *(const float4*)(x + (size_t)(row0 + r) * K + kt + s * 4);
            xs[s * 4 + 0][r] = v.x;
            xs[s * 4 + 1][r] = v.y;
            xs[s * 4 + 2][r] = v.z;
            xs[s * 4 + 3][r] = v.w;
        }
#pragma unroll
        for (int i = 0; i < 3; i++) {
            int f = tid + i * 256;
            int k = f / 48, n4 = f % 48;
            float4 v = *(const float4*)(WT + (size_t)(kt + k) * BN + n4 * 4);
            *(float4*)&ws[k][n4 * 4] = v;
        }
        __syncthreads();

#pragma unroll
        for (int k = 0; k < BK; k++) {
            float a0 = xs[k][2 * tr];
            float a1 = xs[k][2 * tr + 1];
            float bv[12];
#pragma unroll
            for (int j = 0; j < 3; j++) {
                float4 w4 = *(const float4*)&ws[k][tc * 12 + j * 4];
                bv[j * 4 + 0] = w4.x; bv[j * 4 + 1] = w4.y;
                bv[j * 4 + 2] = w4.z; bv[j * 4 + 3] = w4.w;
            }
#pragma unroll
            for (int j = 0; j < 12; j++) {
                acc[0][j] = fmaf(a0, bv[j], acc[0][j]);
                acc[1][j] = fmaf(a1, bv[j], acc[1][j]);
            }
        }
    }

    __syncthreads();
#pragma unroll
    for (int i = 0; i < 2; i++)
#pragma unroll
        for (int j = 0; j < 12; j++)
            zs[2 * tr + i][tc * 12 + j] = acc[i][j];
    __syncthreads();

    const int warp = tid >> 5, lane = tid & 31;
    const int n0 = 2 * lane, n1 = 2 * lane + 1;

#pragma unroll
    for (int rr = 0; rr < 4; rr++) {
        int r    = warp * 4 + rr;
        int grow = row0 + r;

        float sg[3][2];
#pragma unroll
        for (int g = 0; g < 3; g++) {
            float z0 = zs[r][g * 64 + n0] + bt[g * 64 + n0];
            float z1 = zs[r][g * 64 + n1] + bt[g * 64 + n1];
            float c0 = cosf(z0);
            float c1 = cosf(z1);
            float incl = c0 * c1;
#pragma unroll
            for (int off = 1; off < 32; off <<= 1) {
                float t = __shfl_up_sync(0xffffffffu, incl, off);
                if (lane >= off) incl *= t;
            }
            float excl = __shfl_up_sync(0xffffffffu, incl, 1);
            if (lane == 0) excl = 1.0f;
            float q0 = excl * c0;
            float q1 = incl;
            sg[g][0] = sigmoidf_(q0);
            sg[g][1] = sigmoidf_(q1);
        }
        float cv0 = sg[0][0] * tanhf(sg[1][0]);
        float cv1 = sg[0][1] * tanhf(sg[1][1]);
        float h0v = sg[2][0] * tanhf(cv0);
        float h1v = sg[2][1] * tanhf(cv1);

        float s = h0v + h1v;
#pragma unroll
        for (int off = 16; off; off >>= 1) s += __shfl_xor_sync(0xffffffffu, s, off);
        float mu = s * (1.0f / 64.0f);
        float d0 = h0v - mu, d1 = h1v - mu;
        float ssq = d0 * d0 + d1 * d1;
#pragma unroll
        for (int off = 16; off; off >>= 1) ssq += __shfl_xor_sync(0xffffffffu, ssq, off);
        float rinv = rsqrtf(ssq * (1.0f / 64.0f) + EPSV);

        float o0 = d0 * rinv * gmm[n0] + bet[n0];
        float o1 = d1 * rinv * gmm[n1] + bet[n1];

        *(float2*)(hln_out + (size_t)grow * HH + n0) = make_float2(o0, o1);

        if (grow >= NROWS - BB) {
            int bi = grow - (NROWS - BB);
            *(float2*)(hlast + (size_t)bi * HH + n0) = make_float2(o0, o1);
            *(float2*)(clast + (size_t)bi * HH + n0) = make_float2(cv0, cv1);
        }
    }
#endif // !HAS_TC
}

// ================================================================ launch
extern "C" void kernel_launch(void* const* d_in, const int* in_sizes, int n_in,
                              void* d_out, int out_size) {
    const float* inputs = (const float*)d_in[0];
    const float* W0  = (const float*)d_in[1];
    const float* b0  = (const float*)d_in[2];
    const float* th0 = (const float*)d_in[3];
    const float* g0  = (const float*)d_in[4];
    const float* be0 = (const float*)d_in[5];
    const float* W1  = (const float*)d_in[6];
    const float* b1  = (const float*)d_in[7];
    const float* th1 = (const float*)d_in[8];
    const float* g1  = (const float*)d_in[9];
    const float* be1 = (const float*)d_in[10];

    float* out = (float*)d_out;
    const size_t out_main = (size_t)NROWS * HH;
    float* h0last = out + out_main;
    float* c0last = h0last + BB * HH;
    float* h1last = c0last + BB * HH;
    float* c1last = h1last + BB * HH;

    float *h0p, *wt0p, *wt1p;
    __nv_bfloat16 *b0hi, *b0lo, *b1hi, *b1lo;
    cudaGetSymbolAddress((void**)&h0p,  g_h0);
    cudaGetSymbolAddress((void**)&wt0p, g_WT0);
    cudaGetSymbolAddress((void**)&wt1p, g_WT1);
    cudaGetSymbolAddress((void**)&b0hi, g_B0hi);
    cudaGetSymbolAddress((void**)&b0lo, g_B0lo);
    cudaGetSymbolAddress((void**)&b1hi, g_B1hi);
    cudaGetSymbolAddress((void**)&b1lo, g_B1lo);

    cudaFuncSetAttribute(qlstm_tc_kernel<8>,
                         cudaFuncAttributeMaxDynamicSharedMemorySize, SMEM_TOTAL);
    cudaFuncSetAttribute(qlstm_tc_kernel<1>,
                         cudaFuncAttributeMaxDynamicSharedMemorySize, SMEM_TOTAL);

    // Prologs (both tiny; each path uses its own)
    prep_w_kernel<<<(8 * NG * 64 + 255) / 256, 256>>>(W0, W1);
    transpose_w_kernel<<<(DDIM * NG + 255) / 256, 256>>>(W0, W1);

    // Tensor-core path (arch-specific targets; no-ops otherwise)
    qlstm_tc_kernel<8><<<NROWS / 128, 128, SMEM_TOTAL>>>(
        inputs, b0hi, b0lo, b0, th0, g0, be0, h0p, h0last, c0last);
    qlstm_tc_kernel<1><<<NROWS / 128, 128, SMEM_TOTAL>>>(
        h0p, b1hi, b1lo, b1, th1, g1, be1, out, h1last, c1last);

    // Scalar fallback path (non-arch-specific targets; no-ops otherwise)
    qlstm_layer_kernel<DDIM><<<NROWS / 32, 256>>>(
        inputs, wt0p, b0, th0, g0, be0, h0p, h0last, c0last);
    qlstm_layer_kernel<HH><<<NROWS / 32, 256>>>(
        h0p, wt1p, b1, th1, g1, be1, out, h1last, c1last);
}

// round 4
// speedup vs baseline: 8.1364x; 2.0571x over previous
#include <cuda_runtime.h>
#include <cuda_bf16.h>
#include <math.h>
#include <stdint.h>

// ---------------------------------------------------------------- constants
#define TT     512
#define BB     128
#define DDIM   512
#define HH     64
#define NROWS  (TT * BB)          // 65536 independent (t,b) rows
#define NG     192                // 3 gates (i, g, o) x 64 qubits
#define EPSV   1e-5f

// Arch-specific feature gate: tcgen05 exists only on sm_10xa targets.
#if defined(__CUDA_ARCH__) && (defined(__CUDA_ARCH_FEAT_SM103_ALL) || \
    defined(__CUDA_ARCH_FEAT_SM100_ALL) || defined(__CUDA_ARCH_SPECIFIC__))
#define HAS_TC 1
#endif

// dynamic SMEM layout, single-buffered (2 CTAs/SM)
#define OFF_A_HI   0              // 16384  (128 rows x 64 bf16, SW128)
#define OFF_A_LO   16384          // 16384
#define OFF_B_HI   32768          // 24576  (192 rows x 64 bf16, SW128)
#define OFF_B_LO   57344          // 24576
#define OFF_MISC   81920          // tmem ptr, mbarrier, bt/gamma/beta
#define SMEM_TOTAL 83968

// idesc: kind::f16, bf16 x bf16 -> f32, M=128, N=192
#define IDESC ((1u << 4) | (1u << 7) | (1u << 10) | ((NG / 8) << 17) | ((128 / 16) << 24))

// ---------------------------------------------------------------- scratch
__device__ float          g_h0[NROWS * HH];      // scalar-fallback intermediate
__device__ __nv_bfloat16  g_B0hi[8 * NG * 64];   // W0: 8 K-chunks, SW128 swizzled
__device__ __nv_bfloat16  g_B0lo[8 * NG * 64];
__device__ __nv_bfloat16  g_B1hi[NG * 64];       // W1: 1 K-chunk
__device__ __nv_bfloat16  g_B1lo[NG * 64];
__device__ __nv_bfloat16  g_A1hi[NROWS * HH];    // layer-0 out, A-operand swizzled
__device__ __nv_bfloat16  g_A1lo[NROWS * HH];
__device__ float          g_WT0[DDIM * NG];      // scalar path: W0 K-major
__device__ float          g_WT1[HH * NG];        // scalar path: W1 K-major

// ================================================================ prolog kernels
__global__ void transpose_w_kernel(const float* __restrict__ W0,
                                   const float* __restrict__ W1) {
#ifndef HAS_TC
    int idx = blockIdx.x * blockDim.x + threadIdx.x;
    if (idx < DDIM * NG) {
        int k = idx / NG, n = idx % NG;
        g_WT0[idx] = W0[(size_t)(64 + n) * (DDIM + HH) + k];
    }
    if (idx < HH * NG) {
        int k = idx / NG, n = idx % NG;
        g_WT1[idx] = W1[(size_t)(64 + n) * (HH + HH) + k];
    }
#endif
}

// Split W (gates 1..3, first K cols) into bf16 hi/lo, B-operand SW128 layout.
__global__ void prep_w_kernel(const float* __restrict__ W0,
                              const float* __restrict__ W1) {
#ifdef HAS_TC
    int idx = blockIdx.x * blockDim.x + threadIdx.x;
    if (idx < 8 * NG * 64) {
        int c   = idx / (NG * 64);
        int rem = idx % (NG * 64);
        int n   = rem / 64, kl = rem % 64;
        float w = W0[(size_t)(64 + n) * (DDIM + HH) + c * 64 + kl];
        __nv_bfloat16 hi = __float2bfloat16(w);
        __nv_bfloat16 lo = __float2bfloat16(w - __bfloat162float(hi));
        uint32_t boff = ((uint32_t)(n >> 3)) * 1024 + ((uint32_t)(n & 7)) * 128 + kl * 2;
        boff ^= ((boff >> 3) & 0x70);
        g_B0hi[(size_t)c * (NG * 64) + boff / 2] = hi;
        g_B0lo[(size_t)c * (NG * 64) + boff / 2] = lo;
    }
    if (idx < NG * 64) {
        int n = idx / 64, kl = idx % 64;
        float w = W1[(size_t)(64 + n) * (HH + HH) + kl];
        __nv_bfloat16 hi = __float2bfloat16(w);
        __nv_bfloat16 lo = __float2bfloat16(w - __bfloat162float(hi));
        uint32_t boff = ((uint32_t)(n >> 3)) * 1024 + ((uint32_t)(n & 7)) * 128 + kl * 2;
        boff ^= ((boff >> 3) & 0x70);
        g_B1hi[boff / 2] = hi;
        g_B1lo[boff / 2] = lo;
    }
#endif
}

// ================================================================ PTX helpers
#ifdef HAS_TC
static __device__ __forceinline__ uint32_t smem_u32(const void* p) {
    uint32_t a;
    asm("{ .reg .u64 t; cvta.to.shared.u64 t, %1; cvt.u32.u64 %0, t; }"
        : "=r"(a) : "l"(p));
    return a;
}
static __device__ __forceinline__ uint32_t elect1() {
    uint32_t p;
    asm volatile("{\n .reg .pred p;\n elect.sync _|p, 0xFFFFFFFF;\n selp.b32 %0,1,0,p;\n}"
                 : "=r"(p));
    return p;
}
static __device__ __forceinline__ uint64_t sdesc(uint32_t addr) {
    return (2ull << 61) | (1ull << 46) | (64ull << 32) | (1ull << 16)
         | ((uint64_t)(addr >> 4) & 0x3FFF);
}
static __device__ __forceinline__ void mma_bf16_ss(uint32_t d, uint64_t ad, uint64_t bd,
                                                   uint32_t idesc, bool accum) {
    uint32_t en = accum ? 1u : 0u;
    asm volatile(
        "{\n\t"
        ".reg .pred p;\n\t"
        "setp.ne.u32 p, %5, 0;\n\t"
        "tcgen05.mma.cta_group::1.kind::f16 [%0], %1, %2, %3, {%4, %4, %4, %4}, p;\n\t"
        "}"
        :: "r"(d), "l"(ad), "l"(bd), "r"(idesc), "r"(0u), "r"(en)
        : "memory");
}
static __device__ __forceinline__ void mbar_wait(uint32_t mbar, uint32_t parity) {
    uint32_t done;
    asm volatile(
        "{\n .reg .pred p;\n"
        " mbarrier.try_wait.parity.acquire.cta.shared::cta.b64 p, [%1], %2;\n"
        " selp.b32 %0, 1, 0, p;\n}"
        : "=r"(done) : "r"(mbar), "r"(parity) : "memory");
    if (!done) {
        asm volatile(
            "{\n .reg .pred P1;\n"
            "WL%=:\n"
            " mbarrier.try_wait.parity.acquire.cta.shared::cta.b64 P1, [%0], %1, 0x989680;\n"
            " @P1 bra.uni WD%=;\n"
            " bra.uni WL%=;\n"
            "WD%=:\n}"
            :: "r"(mbar), "r"(parity) : "memory");
    }
}
#define TC_WAIT_LD() asm volatile("tcgen05.wait::ld.sync.aligned;" ::: "memory")
#define LDTM_X32(r, addr)                                              \
    asm volatile(                                                       \
        "tcgen05.ld.sync.aligned.32x32b.x32.b32 "                       \
        "{%0, %1, %2, %3, %4, %5, %6, %7, "                             \
        " %8, %9, %10, %11, %12, %13, %14, %15, "                       \
        " %16, %17, %18, %19, %20, %21, %22, %23, "                     \
        " %24, %25, %26, %27, %28, %29, %30, %31}, [%32];"              \
        : "=r"((r)[0]),  "=r"((r)[1]),  "=r"((r)[2]),  "=r"((r)[3]),    \
          "=r"((r)[4]),  "=r"((r)[5]),  "=r"((r)[6]),  "=r"((r)[7]),    \
          "=r"((r)[8]),  "=r"((r)[9]),  "=r"((r)[10]), "=r"((r)[11]),   \
          "=r"((r)[12]), "=r"((r)[13]), "=r"((r)[14]), "=r"((r)[15]),   \
          "=r"((r)[16]), "=r"((r)[17]), "=r"((r)[18]), "=r"((r)[19]),   \
          "=r"((r)[20]), "=r"((r)[21]), "=r"((r)[22]), "=r"((r)[23]),   \
          "=r"((r)[24]), "=r"((r)[25]), "=r"((r)[26]), "=r"((r)[27]),   \
          "=r"((r)[28]), "=r"((r)[29]), "=r"((r)[30]), "=r"((r)[31])    \
        : "r"(addr))

// fast approximate transcendentals (MUFU; errors ~1e-6 class)
static __device__ __forceinline__ float fex2(float x) {
    float y; asm("ex2.approx.f32 %0, %1;" : "=f"(y) : "f"(x)); return y;
}
static __device__ __forceinline__ float frcp(float x) {
    float y; asm("rcp.approx.f32 %0, %1;" : "=f"(y) : "f"(x)); return y;
}
static __device__ __forceinline__ float fsigmoid(float q) {
    return frcp(1.0f + fex2(q * -1.4426950408889634f));
}
static __device__ __forceinline__ float ftanh(float x) {
    // tanh(x) = 1 - 2/(exp(2x)+1); args here are in [0, ~0.8]
    return 1.0f - 2.0f * frcp(fex2(x * 2.8853900817779268f) + 1.0f);
}
#endif // HAS_TC

// ================================================================ tensor kernel
// CTA = 128 rows x 192 gate cols; K in 64-chunks, single-buffered SMEM (82KB ->
// 2 CTAs/SM); tcgen05 bf16 3-term split GEMM; fused ILP-friendly epilogue.
// PRE: A comes pre-split/pre-swizzled (layer 1); WOUT: emit bf16 A-tiles (layer 0).
template <int NC, bool PRE, bool WOUT>
__global__ void __launch_bounds__(128, 2)
qlstm_tc_kernel(const float* __restrict__ x,               // [NROWS, NC*64] (if !PRE)
                const __nv_bfloat16* __restrict__ Ahi_g,   // (if PRE)
                const __nv_bfloat16* __restrict__ Alo_g,
                const __nv_bfloat16* __restrict__ Bhi_g,
                const __nv_bfloat16* __restrict__ Blo_g,
                const float* __restrict__ bvec,
                const float* __restrict__ thvec,
                const float* __restrict__ gamma,
                const float* __restrict__ beta,
                float* __restrict__ hout,                  // fp32 out (if !WOUT)
                __nv_bfloat16* __restrict__ Ohi_g,         // bf16 out (if WOUT)
                __nv_bfloat16* __restrict__ Olo_g,
                float* __restrict__ hlast,
                float* __restrict__ clast)
{
#ifdef HAS_TC
    constexpr int K = NC * 64;
    extern __shared__ __align__(1024) char smem[];
    const uint32_t sb = smem_u32(smem);
    const int tid = threadIdx.x, wid = tid >> 5, lane = tid & 31;
    const int row0 = blockIdx.x * 128;

    float* bt  = (float*)(smem + OFF_MISC + 32);
    float* gm  = bt + NG;
    float* bet = gm + HH;
    for (int i = tid; i < NG; i += 128) bt[i] = bvec[64 + i] + thvec[64 + i];
    if (tid < HH) { gm[tid] = gamma[tid]; bet[tid] = beta[tid]; }

    const uint32_t mb = sb + OFF_MISC + 8;
    if (wid == 0) {
        asm volatile("tcgen05.alloc.cta_group::1.sync.aligned.shared::cta.b32 [%0], %1;"
                     :: "r"(sb + OFF_MISC), "r"(256u) : "memory");
        asm volatile("tcgen05.relinquish_alloc_permit.cta_group::1.sync.aligned;");
    }
    if (tid == 0) {
        asm volatile("mbarrier.init.shared.b64 [%0], %1;" :: "r"(mb), "r"(1u) : "memory");
    }
    __syncthreads();
    uint32_t tmem;
    asm volatile("ld.shared.b32 %0, [%1];" : "=r"(tmem) : "r"(sb + OFF_MISC));

    // ---------------- K-chunk loop (single buffer; wait on previous commit) ---
    for (int c = 0; c < NC; c++) {
        if (c > 0) mbar_wait(mb, (c - 1) & 1);

        if (PRE) {
            // A pre-split & pre-swizzled: contiguous 16KB hi + 16KB lo copy
            const uint4* srcH = (const uint4*)(Ahi_g + (size_t)row0 * 64);
            const uint4* srcL = (const uint4*)(Alo_g + (size_t)row0 * 64);
            uint4* dstH = (uint4*)(smem + OFF_A_HI);
            uint4* dstL = (uint4*)(smem + OFF_A_LO);
#pragma unroll
            for (int j = 0; j < 8; j++) {
                dstH[tid + j * 128] = srcH[tid + j * 128];
                dstL[tid + j * 128] = srcL[tid + j * 128];
            }
        } else {
            // A: fp32 -> bf16 hi/lo, SW128-swizzled STS
            char* ah = smem + OFF_A_HI;
            char* al = smem + OFF_A_LO;
#pragma unroll
            for (int j = 0; j < 16; j++) {
                int idx = tid + j * 128;
                int r = idx >> 4, s = idx & 15;
                float4 v = *(const float4*)(x + (size_t)(row0 + r) * K + c * 64 + s * 4);
                __nv_bfloat16 hx = __float2bfloat16(v.x);
                __nv_bfloat16 hy = __float2bfloat16(v.y);
                __nv_bfloat16 hz = __float2bfloat16(v.z);
                __nv_bfloat16 hw = __float2bfloat16(v.w);
                __nv_bfloat16 lx = __float2bfloat16(v.x - __bfloat162float(hx));
                __nv_bfloat16 ly = __float2bfloat16(v.y - __bfloat162float(hy));
                __nv_bfloat16 lz = __float2bfloat16(v.z - __bfloat162float(hz));
                __nv_bfloat16 lw = __float2bfloat16(v.w - __bfloat162float(hw));
                uint32_t off = (uint32_t)r * 128 + (uint32_t)s * 8;
                off ^= ((off >> 3) & 0x70);
                *(__nv_bfloat162*)(ah + off)     = __nv_bfloat162(hx, hy);
                *(__nv_bfloat162*)(ah + off + 4) = __nv_bfloat162(hz, hw);
                *(__nv_bfloat162*)(al + off)     = __nv_bfloat162(lx, ly);
                *(__nv_bfloat162*)(al + off + 4) = __nv_bfloat162(lz, lw);
            }
        }
        {   // B: pre-swizzled, raw float4 copy (L2-resident after first wave)
            const float4* bh = (const float4*)(Bhi_g + (size_t)c * (NG * 64));
            const float4* bl = (const float4*)(Blo_g + (size_t)c * (NG * 64));
            float4* sh = (float4*)(smem + OFF_B_HI);
            float4* sl = (float4*)(smem + OFF_B_LO);
#pragma unroll
            for (int j = 0; j < 12; j++) {
                int idx = tid + j * 128;
                sh[idx] = bh[idx];
                sl[idx] = bl[idx];
            }
        }
        __syncthreads();

        if (wid == 0 && elect1()) {
            asm volatile("fence.proxy.async.shared::cta;" ::: "memory");
            uint64_t aH = sdesc(sb + OFF_A_HI);
            uint64_t aL = sdesc(sb + OFF_A_LO);
            uint64_t bH = sdesc(sb + OFF_B_HI);
            uint64_t bL = sdesc(sb + OFF_B_LO);
#pragma unroll
            for (int ks = 0; ks < 4; ks++)
                mma_bf16_ss(tmem, aH + ks * 2, bH + ks * 2, IDESC, !(c == 0 && ks == 0));
#pragma unroll
            for (int ks = 0; ks < 4; ks++)
                mma_bf16_ss(tmem, aH + ks * 2, bL + ks * 2, IDESC, true);
#pragma unroll
            for (int ks = 0; ks < 4; ks++)
                mma_bf16_ss(tmem, aL + ks * 2, bH + ks * 2, IDESC, true);
            asm volatile(
                "tcgen05.commit.cta_group::1.mbarrier::arrive::one.shared::cluster.b64 [%0];"
                :: "r"(mb) : "memory");
        }
        if (c + 1 < NC) __syncthreads();   // keep loaders from racing ahead of wait
    }

    mbar_wait(mb, (NC - 1) & 1);
    asm volatile("tcgen05.fence::after_thread_sync;" ::: "memory");

    // ---------------- epilogue: thread = TMEM lane = row --------------------
    const int myrow = row0 + wid * 32 + lane;
    const bool tail = (myrow >= NROWS - BB);
    float hv[64];
    float cs[64];
    uint32_t* ru = (uint32_t*)cs;

#pragma unroll
    for (int g = 0; g < 3; g++) {
        LDTM_X32(ru,      tmem + g * 64);
        LDTM_X32(ru + 32, tmem + g * 64 + 32);
        TC_WAIT_LD();
        // all-independent cos
#pragma unroll
        for (int j = 0; j < 64; j++)
            cs[j] = __cosf(__uint_as_float(ru[j]) + bt[g * 64 + j]);
        // grouped cumprod: 8 serial chains of 8 (ILP=8)
#pragma unroll
        for (int g8 = 0; g8 < 8; g8++)
#pragma unroll
            for (int j = 1; j < 8; j++)
                cs[g8 * 8 + j] *= cs[g8 * 8 + j - 1];
        // group-prefix scan + fixup
        float pref = 1.0f;
#pragma unroll
        for (int g8 = 0; g8 < 8; g8++) {
            float tot = cs[g8 * 8 + 7];
#pragma unroll
            for (int j = 0; j < 8; j++)
                cs[g8 * 8 + j] *= pref;
            pref *= tot;
        }
        // gate combine (independent per element)
        if (g == 0) {
#pragma unroll
            for (int j = 0; j < 64; j++) hv[j] = fsigmoid(cs[j]);
        } else if (g == 1) {
#pragma unroll
            for (int j = 0; j < 64; j++) hv[j] *= ftanh(fsigmoid(cs[j]));   // c
        } else {
#pragma unroll
            for (int j = 0; j < 64; j++) hv[j] = fsigmoid(cs[j]) * ftanh(hv[j]);  // h
        }
        if (g == 1 && tail) {
            float4* cd = (float4*)(clast + (size_t)(myrow - (NROWS - BB)) * HH);
#pragma unroll
            for (int j = 0; j < 16; j++)
                cd[j] = make_float4(hv[4*j], hv[4*j+1], hv[4*j+2], hv[4*j+3]);
        }
    }

    // layernorm over the 64 in-register values
    float s = 0.0f;
#pragma unroll
    for (int j = 0; j < 64; j++) s += hv[j];
    float mu = s * (1.0f / 64.0f);
    float ss = 0.0f;
#pragma unroll
    for (int j = 0; j < 64; j++) { float d = hv[j] - mu; ss += d * d; }
    float rinv = rsqrtf(ss * (1.0f / 64.0f) + EPSV);
#pragma unroll
    for (int j = 0; j < 64; j++) hv[j] = (hv[j] - mu) * rinv * gm[j] + bet[j];

    if (WOUT) {
        // emit bf16 hi/lo in A-operand SW128 layout (row atoms of 8 x 128B)
        char* ohi = (char*)Ohi_g + ((size_t)(myrow >> 3) << 10);
        char* olo = (char*)Olo_g + ((size_t)(myrow >> 3) << 10);
#pragma unroll
        for (int j4 = 0; j4 < 8; j4++) {
            __nv_bfloat162 ph[4], pl[4];
#pragma unroll
            for (int q = 0; q < 4; q++) {
                float v0 = hv[j4 * 8 + q * 2], v1 = hv[j4 * 8 + q * 2 + 1];
                __nv_bfloat16 h0 = __float2bfloat16(v0);
                __nv_bfloat16 h1 = __float2bfloat16(v1);
                ph[q] = __nv_bfloat162(h0, h1);
                pl[q] = __nv_bfloat162(__float2bfloat16(v0 - __bfloat162float(h0)),
                                       __float2bfloat16(v1 - __bfloat162float(h1)));
            }
            uint32_t off = ((uint32_t)(myrow & 7) << 7) + j4 * 16;
            off ^= ((off >> 3) & 0x70);
            *(uint4*)(ohi + off) = *(uint4*)ph;
            *(uint4*)(olo + off) = *(uint4*)pl;
        }
        if (tail) {
            float4* hd = (float4*)(hlast + (size_t)(myrow - (NROWS - BB)) * HH);
#pragma unroll
            for (int j = 0; j < 16; j++)
                hd[j] = make_float4(hv[4*j], hv[4*j+1], hv[4*j+2], hv[4*j+3]);
        }
    } else {
        float4* od = (float4*)(hout + (size_t)myrow * HH);
#pragma unroll
        for (int j = 0; j < 16; j++)
            od[j] = make_float4(hv[4*j], hv[4*j+1], hv[4*j+2], hv[4*j+3]);
        if (tail) {
            float4* hd = (float4*)(hlast + (size_t)(myrow - (NROWS - BB)) * HH);
#pragma unroll
            for (int j = 0; j < 16; j++)
                hd[j] = make_float4(hv[4*j], hv[4*j+1], hv[4*j+2], hv[4*j+3]);
        }
    }

    asm volatile("tcgen05.fence::before_thread_sync;" ::: "memory");
    __syncthreads();
    if (wid == 0) {
        asm volatile("tcgen05.dealloc.cta_group::1.sync.aligned.b32 %0, %1;"
                     :: "r"(tmem), "r"(256u));
    }
#endif // HAS_TC
}

// ================================================================ scalar kernel
// Fallback for non-arch-specific targets (empty on sm_103a-specific SASS).
__device__ __forceinline__ float sigmoidf_(float x) {
    return 1.0f / (1.0f + expf(-x));
}

template <int K>
__global__ __launch_bounds__(256)
void qlstm_layer_kernel(const float* __restrict__ x,
                        const float* __restrict__ WT,
                        const float* __restrict__ bvec,
                        const float* __restrict__ thvec,
                        const float* __restrict__ gamma,
                        const float* __restrict__ beta,
                        float* __restrict__ hln_out,
                        float* __restrict__ hlast,
                        float* __restrict__ clast)
{
#ifndef HAS_TC
    constexpr int BM = 32, BN = NG, BK = 16;
    __shared__ float xs[BK][BM];
    __shared__ __align__(16) float ws[BK][BN];
    __shared__ float zs[BM][BN];
    __shared__ float bt[BN];
    __shared__ float gmm[HH], bet[HH];

    const int tid  = threadIdx.x;
    const int row0 = blockIdx.x * BM;

    if (tid < NG) bt[tid] = bvec[64 + tid] + thvec[64 + tid];
    if (tid < HH) { gmm[tid] = gamma[tid]; bet[tid] = beta[tid]; }

    const int tc = tid & 15;
    const int tr = tid >> 4;

    float acc[2][12];
#pragma unroll
    for (int i = 0; i < 2; i++)
#pragma unroll
        for (int j = 0; j < 12; j++) acc[i][j] = 0.0f;

    for (int kt = 0; kt < K; kt += BK) {
        __syncthreads();
        if (tid < 128) {
            int r = tid >> 2, s = tid & 3;
            float4 v = *(const float4*)(x + (size_t)(row0 + r) * K + kt + s * 4);
            xs[s * 4 + 0][r] = v.x;
            xs[s * 4 + 1][r] = v.y;
            xs[s * 4 + 2][r] = v.z;
            xs[s * 4 + 3][r] = v.w;
        }
#pragma unroll
        for (int i = 0; i < 3; i++) {
            int f = tid + i * 256;
            int k = f / 48, n4 = f % 48;
            float4 v = *(const float4*)(WT + (size_t)(kt + k) * BN + n4 * 4);
            *(float4*)&ws[k][n4 * 4] = v;
        }
        __syncthreads();

#pragma unroll
        for (int k = 0; k < BK; k++) {
            float a0 = xs[k][2 * tr];
            float a1 = xs[k][2 * tr + 1];
            float bv[12];
#pragma unroll
            for (int j = 0; j < 3; j++) {
                float4 w4 = *(const float4*)&ws[k][tc * 12 + j * 4];
                bv[j * 4 + 0] = w4.x; bv[j * 4 + 1] = w4.y;
                bv[j * 4 + 2] = w4.z; bv[j * 4 + 3] = w4.w;
            }
#pragma unroll
            for (int j = 0; j < 12; j++) {
                acc[0][j] = fmaf(a0, bv[j], acc[0][j]);
                acc[1][j] = fmaf(a1, bv[j], acc[1][j]);
            }
        }
    }

    __syncthreads();
#pragma unroll
    for (int i = 0; i < 2; i++)
#pragma unroll
        for (int j = 0; j < 12; j++)
            zs[2 * tr + i][tc * 12 + j] = acc[i][j];
    __syncthreads();

    const int warp = tid >> 5, lane = tid & 31;
    const int n0 = 2 * lane, n1 = 2 * lane + 1;

#pragma unroll
    for (int rr = 0; rr < 4; rr++) {
        int r    = warp * 4 + rr;
        int grow = row0 + r;

        float sg[3][2];
#pragma unroll
        for (int g = 0; g < 3; g++) {
            float z0 = zs[r][g * 64 + n0] + bt[g * 64 + n0];
            float z1 = zs[r][g * 64 + n1] + bt[g * 64 + n1];
            float c0 = cosf(z0);
            float c1 = cosf(z1);
            float incl = c0 * c1;
#pragma unroll
            for (int off = 1; off < 32; off <<= 1) {
                float t = __shfl_up_sync(0xffffffffu, incl, off);
                if (lane >= off) incl *= t;
            }
            float excl = __shfl_up_sync(0xffffffffu, incl, 1);
            if (lane == 0) excl = 1.0f;
            float q0 = excl * c0;
            float q1 = incl;
            sg[g][0] = sigmoidf_(q0);
            sg[g][1] = sigmoidf_(q1);
        }
        float cv0 = sg[0][0] * tanhf(sg[1][0]);
        float cv1 = sg[0][1] * tanhf(sg[1][1]);
        float h0v = sg[2][0] * tanhf(cv0);
        float h1v = sg[2][1] * tanhf(cv1);

        float s = h0v + h1v;
#pragma unroll
        for (int off = 16; off; off >>= 1) s += __shfl_xor_sync(0xffffffffu, s, off);
        float mu = s * (1.0f / 64.0f);
        float d0 = h0v - mu, d1 = h1v - mu;
        float ssq = d0 * d0 + d1 * d1;
#pragma unroll
        for (int off = 16; off; off >>= 1) ssq += __shfl_xor_sync(0xffffffffu, ssq, off);
        float rinv = rsqrtf(ssq * (1.0f / 64.0f) + EPSV);

        float o0 = d0 * rinv * gmm[n0] + bet[n0];
        float o1 = d1 * rinv * gmm[n1] + bet[n1];

        *(float2*)(hln_out + (size_t)grow * HH + n0) = make_float2(o0, o1);

        if (grow >= NROWS - BB) {
            int bi = grow - (NROWS - BB);
            *(float2*)(hlast + (size_t)bi * HH + n0) = make_float2(o0, o1);
            *(float2*)(clast + (size_t)bi * HH + n0) = make_float2(cv0, cv1);
        }
    }
#endif // !HAS_TC
}

// ================================================================ launch
extern "C" void kernel_launch(void* const* d_in, const int* in_sizes, int n_in,
                              void* d_out, int out_size) {
    const float* inputs = (const float*)d_in[0];
    const float* W0  = (const float*)d_in[1];
    const float* b0  = (const float*)d_in[2];
    const float* th0 = (const float*)d_in[3];
    const float* g0  = (const float*)d_in[4];
    const float* be0 = (const float*)d_in[5];
    const float* W1  = (const float*)d_in[6];
    const float* b1  = (const float*)d_in[7];
    const float* th1 = (const float*)d_in[8];
    const float* g1  = (const float*)d_in[9];
    const float* be1 = (const float*)d_in[10];

    float* out = (float*)d_out;
    const size_t out_main = (size_t)NROWS * HH;
    float* h0last = out + out_main;
    float* c0last = h0last + BB * HH;
    float* h1last = c0last + BB * HH;
    float* c1last = h1last + BB * HH;

    float *h0p, *wt0p, *wt1p;
    __nv_bfloat16 *b0hi, *b0lo, *b1hi, *b1lo, *a1hi, *a1lo;
    cudaGetSymbolAddress((void**)&h0p,  g_h0);
    cudaGetSymbolAddress((void**)&wt0p, g_WT0);
    cudaGetSymbolAddress((void**)&wt1p, g_WT1);
    cudaGetSymbolAddress((void**)&b0hi, g_B0hi);
    cudaGetSymbolAddress((void**)&b0lo, g_B0lo);
    cudaGetSymbolAddress((void**)&b1hi, g_B1hi);
    cudaGetSymbolAddress((void**)&b1lo, g_B1lo);
    cudaGetSymbolAddress((void**)&a1hi, g_A1hi);
    cudaGetSymbolAddress((void**)&a1lo, g_A1lo);

    cudaFuncSetAttribute((const void*)qlstm_tc_kernel<8, false, true>,
                         cudaFuncAttributeMaxDynamicSharedMemorySize, SMEM_TOTAL);
    cudaFuncSetAttribute((const void*)qlstm_tc_kernel<1, true, false>,
                         cudaFuncAttributeMaxDynamicSharedMemorySize, SMEM_TOTAL);

    prep_w_kernel<<<(8 * NG * 64 + 255) / 256, 256>>>(W0, W1);
    transpose_w_kernel<<<(DDIM * NG + 255) / 256, 256>>>(W0, W1);

    // Tensor-core path (arch-specific targets; no-ops otherwise)
    qlstm_tc_kernel<8, false, true><<<NROWS / 128, 128, SMEM_TOTAL>>>(
        inputs, nullptr, nullptr, b0hi, b0lo, b0, th0, g0, be0,
        nullptr, a1hi, a1lo, h0last, c0last);
    qlstm_tc_kernel<1, true, false><<<NROWS / 128, 128, SMEM_TOTAL>>>(
        nullptr, a1hi, a1lo, b1hi, b1lo, b1, th1, g1, be1,
        out, nullptr, nullptr, h1last, c1last);

    // Scalar fallback path (non-arch-specific targets; no-ops otherwise)
    qlstm_layer_kernel<DDIM><<<NROWS / 32, 256>>>(
        inputs, wt0p, b0, th0, g0, be0, h0p, h0last, c0last);
    qlstm_layer_kernel<HH><<<NROWS / 32, 256>>>(
        h0p, wt1p, b1, th1, g1, be1, out, h1last, c1last);
}

// round 5
// speedup vs baseline: 10.4475x; 1.2840x over previous
#include <cuda_runtime.h>
#include <cuda_bf16.h>
#include <math.h>
#include <stdint.h>

// ---------------------------------------------------------------- constants
#define TT     512
#define BB     128
#define DDIM   512
#define HH     64
#define NROWS  (TT * BB)          // 65536 independent (t,b) rows
#define NG     192                // 3 gates (i, g, o) x 64 qubits
#define EPSV   1e-5f

// Arch-specific feature gate: tcgen05 exists only on sm_10xa targets.
#if defined(__CUDA_ARCH__) && (defined(__CUDA_ARCH_FEAT_SM103_ALL) || \
    defined(__CUDA_ARCH_FEAT_SM100_ALL) || defined(__CUDA_ARCH_SPECIFIC__))
#define HAS_TC 1
#endif

// dynamic SMEM layout, single-buffered (2 CTAs/SM; TMEM-capped anyway)
#define OFF_A_HI   0              // 16384  (128 rows x 64 bf16, SW128)
#define OFF_A_LO   16384          // 16384
#define OFF_B_HI   32768          // 24576  (192 rows x 64 bf16, SW128)
#define OFF_B_LO   57344          // 24576
#define OFF_MISC   81920          // tmem ptr, mbarrier, params, exchange bufs
#define SMEM_TOTAL 86016

// idesc: kind::f16, bf16 x bf16 -> f32, M=128, N=192
#define IDESC ((1u << 4) | (1u << 7) | (1u << 10) | ((NG / 8) << 17) | ((128 / 16) << 24))

// ---------------------------------------------------------------- scratch
__device__ float          g_h0[NROWS * HH];      // scalar-fallback intermediate
__device__ __nv_bfloat16  g_B0hi[8 * NG * 64];   // W0: 8 K-chunks, SW128 swizzled
__device__ __nv_bfloat16  g_B0lo[8 * NG * 64];
__device__ __nv_bfloat16  g_B1hi[NG * 64];       // W1: 1 K-chunk
__device__ __nv_bfloat16  g_B1lo[NG * 64];
__device__ float          g_WT0[DDIM * NG];      // scalar path: W0 K-major
__device__ float          g_WT1[HH * NG];        // scalar path: W1 K-major

// ================================================================ prolog kernels
__global__ void transpose_w_kernel(const float* __restrict__ W0,
                                   const float* __restrict__ W1) {
#ifndef HAS_TC
    int idx = blockIdx.x * blockDim.x + threadIdx.x;
    if (idx < DDIM * NG) {
        int k = idx / NG, n = idx % NG;
        g_WT0[idx] = W0[(size_t)(64 + n) * (DDIM + HH) + k];
    }
    if (idx < HH * NG) {
        int k = idx / NG, n = idx % NG;
        g_WT1[idx] = W1[(size_t)(64 + n) * (HH + HH) + k];
    }
#endif
}

// Split W (gates 1..3, first K cols) into bf16 hi/lo, B-operand SW128 layout.
__global__ void prep_w_kernel(const float* __restrict__ W0,
                              const float* __restrict__ W1) {
#ifdef HAS_TC
    int idx = blockIdx.x * blockDim.x + threadIdx.x;
    if (idx < 8 * NG * 64) {
        int c   = idx / (NG * 64);
        int rem = idx % (NG * 64);
        int n   = rem / 64, kl = rem % 64;
        float w = W0[(size_t)(64 + n) * (DDIM + HH) + c * 64 + kl];
        __nv_bfloat16 hi = __float2bfloat16(w);
        __nv_bfloat16 lo = __float2bfloat16(w - __bfloat162float(hi));
        uint32_t boff = ((uint32_t)(n >> 3)) * 1024 + ((uint32_t)(n & 7)) * 128 + kl * 2;
        boff ^= ((boff >> 3) & 0x70);
        g_B0hi[(size_t)c * (NG * 64) + boff / 2] = hi;
        g_B0lo[(size_t)c * (NG * 64) + boff / 2] = lo;
    }
    if (idx < NG * 64) {
        int n = idx / 64, kl = idx % 64;
        float w = W1[(size_t)(64 + n) * (HH + HH) + kl];
        __nv_bfloat16 hi = __float2bfloat16(w);
        __nv_bfloat16 lo = __float2bfloat16(w - __bfloat162float(hi));
        uint32_t boff = ((uint32_t)(n >> 3)) * 1024 + ((uint32_t)(n & 7)) * 128 + kl * 2;
        boff ^= ((boff >> 3) & 0x70);
        g_B1hi[boff / 2] = hi;
        g_B1lo[boff / 2] = lo;
    }
#endif
}

// ================================================================ PTX helpers
#ifdef HAS_TC
static __device__ __forceinline__ uint32_t smem_u32(const void* p) {
    uint32_t a;
    asm("{ .reg .u64 t; cvta.to.shared.u64 t, %1; cvt.u32.u64 %0, t; }"
        : "=r"(a) : "l"(p));
    return a;
}
static __device__ __forceinline__ uint32_t elect1() {
    uint32_t p;
    asm volatile("{\n .reg .pred p;\n elect.sync _|p, 0xFFFFFFFF;\n selp.b32 %0,1,0,p;\n}"
                 : "=r"(p));
    return p;
}
static __device__ __forceinline__ uint64_t sdesc(uint32_t addr) {
    return (2ull << 61) | (1ull << 46) | (64ull << 32) | (1ull << 16)
         | ((uint64_t)(addr >> 4) & 0x3FFF);
}
static __device__ __forceinline__ void mma_bf16_ss(uint32_t d, uint64_t ad, uint64_t bd,
                                                   uint32_t idesc, bool accum) {
    uint32_t en = accum ? 1u : 0u;
    asm volatile(
        "{\n\t"
        ".reg .pred p;\n\t"
        "setp.ne.u32 p, %5, 0;\n\t"
        "tcgen05.mma.cta_group::1.kind::f16 [%0], %1, %2, %3, {%4, %4, %4, %4}, p;\n\t"
        "}"
        :: "r"(d), "l"(ad), "l"(bd), "r"(idesc), "r"(0u), "r"(en)
        : "memory");
}
static __device__ __forceinline__ void mbar_wait(uint32_t mbar, uint32_t parity) {
    uint32_t done;
    asm volatile(
        "{\n .reg .pred p;\n"
        " mbarrier.try_wait.parity.acquire.cta.shared::cta.b64 p, [%1], %2;\n"
        " selp.b32 %0, 1, 0, p;\n}"
        : "=r"(done) : "r"(mbar), "r"(parity) : "memory");
    if (!done) {
        asm volatile(
            "{\n .reg .pred P1;\n"
            "WL%=:\n"
            " mbarrier.try_wait.parity.acquire.cta.shared::cta.b64 P1, [%0], %1, 0x989680;\n"
            " @P1 bra.uni WD%=;\n"
            " bra.uni WL%=;\n"
            "WD%=:\n}"
            :: "r"(mbar), "r"(parity) : "memory");
    }
}
#define TC_WAIT_LD() asm volatile("tcgen05.wait::ld.sync.aligned;" ::: "memory")
#define LDTM_X32(r, addr)                                              \
    asm volatile(                                                       \
        "tcgen05.ld.sync.aligned.32x32b.x32.b32 "                       \
        "{%0, %1, %2, %3, %4, %5, %6, %7, "                             \
        " %8, %9, %10, %11, %12, %13, %14, %15, "                       \
        " %16, %17, %18, %19, %20, %21, %22, %23, "                     \
        " %24, %25, %26, %27, %28, %29, %30, %31}, [%32];"              \
        : "=r"((r)[0]),  "=r"((r)[1]),  "=r"((r)[2]),  "=r"((r)[3]),    \
          "=r"((r)[4]),  "=r"((r)[5]),  "=r"((r)[6]),  "=r"((r)[7]),    \
          "=r"((r)[8]),  "=r"((r)[9]),  "=r"((r)[10]), "=r"((r)[11]),   \
          "=r"((r)[12]), "=r"((r)[13]), "=r"((r)[14]), "=r"((r)[15]),   \
          "=r"((r)[16]), "=r"((r)[17]), "=r"((r)[18]), "=r"((r)[19]),   \
          "=r"((r)[20]), "=r"((r)[21]), "=r"((r)[22]), "=r"((r)[23]),   \
          "=r"((r)[24]), "=r"((r)[25]), "=r"((r)[26]), "=r"((r)[27]),   \
          "=r"((r)[28]), "=r"((r)[29]), "=r"((r)[30]), "=r"((r)[31])    \
        : "r"(addr))

// fast approximate transcendentals (MUFU; errors ~1e-6 class)
static __device__ __forceinline__ float fex2(float x) {
    float y; asm("ex2.approx.f32 %0, %1;" : "=f"(y) : "f"(x)); return y;
}
static __device__ __forceinline__ float frcp(float x) {
    float y; asm("rcp.approx.f32 %0, %1;" : "=f"(y) : "f"(x)); return y;
}
static __device__ __forceinline__ float fsigmoid(float q) {
    return frcp(1.0f + fex2(q * -1.4426950408889634f));
}
static __device__ __forceinline__ float ftanh(float x) {
    return 1.0f - 2.0f * frcp(fex2(x * 2.8853900817779268f) + 1.0f);
}

// ---------------------------------------------------------------- epilogue half
// Warp pair (w, w+4) shares rows (w&3)*32+lane; each half owns 32 gate columns.
// L0: write h_ln as bf16 hi/lo into SMEM A tile; else write fp32 to global out.
template <bool L0>
static __device__ __forceinline__ void epilogue_half(
    uint32_t tmem, const float* __restrict__ bt,
    const float* __restrict__ gm, const float* __restrict__ bet,
    volatile float* ex0, volatile float* ex1,
    char* ahi, char* alo, float* __restrict__ outp,
    float* __restrict__ hlast, float* __restrict__ clast,
    int half, int rl, int myrow)
{
    float hv[32], cs[32];
    uint32_t* ru = (uint32_t*)cs;
    const int colbase = half * 32;
    const bool tail = (myrow >= NROWS - BB);
    const int tb = myrow - (NROWS - BB);

#pragma unroll
    for (int g = 0; g < 3; g++) {
        LDTM_X32(ru, tmem + g * 64 + colbase);
        TC_WAIT_LD();
#pragma unroll
        for (int j = 0; j < 32; j++)
            cs[j] = __cosf(__uint_as_float(ru[j]) + bt[g * 64 + colbase + j]);
        // local inclusive multiply-scan of 32: 4 chains of 8, then group prefix
#pragma unroll
        for (int g8 = 0; g8 < 4; g8++)
#pragma unroll
            for (int j = 1; j < 8; j++)
                cs[g8 * 8 + j] *= cs[g8 * 8 + j - 1];
        float pref = 1.0f;
#pragma unroll
        for (int g8 = 0; g8 < 4; g8++) {
            float tot = cs[g8 * 8 + 7];
#pragma unroll
            for (int j = 0; j < 8; j++) cs[g8 * 8 + j] *= pref;
            pref *= tot;
        }
        // cross-half prefix: low publishes its total, high multiplies it in
        if (half == 0) ex0[rl] = pref;
        __syncthreads();
        if (half == 1) {
            float p = ex0[rl];
#pragma unroll
            for (int j = 0; j < 32; j++) cs[j] *= p;
        }
        __syncthreads();

        if (g == 0) {
#pragma unroll
            for (int j = 0; j < 32; j++) hv[j] = fsigmoid(cs[j]);
        } else if (g == 1) {
#pragma unroll
            for (int j = 0; j < 32; j++) hv[j] *= ftanh(fsigmoid(cs[j]));   // c
            if (tail) {
                float4* cd = (float4*)(clast + (size_t)tb * HH) + half * 8;
#pragma unroll
                for (int j = 0; j < 8; j++)
                    cd[j] = make_float4(hv[4*j], hv[4*j+1], hv[4*j+2], hv[4*j+3]);
            }
        } else {
#pragma unroll
            for (int j = 0; j < 32; j++) hv[j] = fsigmoid(cs[j]) * ftanh(hv[j]);  // h
        }
    }

    // layernorm across the pair
    float s = 0.0f;
#pragma unroll
    for (int j = 0; j < 32; j++) s += hv[j];
    if (half == 0) ex0[rl] = s; else ex1[rl] = s;
    __syncthreads();
    float mu = (ex0[rl] + ex1[rl]) * (1.0f / 64.0f);
    float q = 0.0f;
#pragma unroll
    for (int j = 0; j < 32; j++) { float d = hv[j] - mu; q += d * d; }
    __syncthreads();
    if (half == 0) ex0[rl] = q; else ex1[rl] = q;
    __syncthreads();
    float rinv = rsqrtf((ex0[rl] + ex1[rl]) * (1.0f / 64.0f) + EPSV);
#pragma unroll
    for (int j = 0; j < 32; j++)
        hv[j] = (hv[j] - mu) * rinv * gm[colbase + j] + bet[colbase + j];

    if (L0) {
        // h_ln -> bf16 hi/lo into SMEM A tile (SW128, layer-1 operand)
#pragma unroll
        for (int j8 = 0; j8 < 4; j8++) {
            __nv_bfloat162 ph[4], pl[4];
#pragma unroll
            for (int p2 = 0; p2 < 4; p2++) {
                float v0 = hv[j8 * 8 + p2 * 2], v1 = hv[j8 * 8 + p2 * 2 + 1];
                __nv_bfloat16 h0 = __float2bfloat16(v0);
                __nv_bfloat16 h1 = __float2bfloat16(v1);
                ph[p2] = __nv_bfloat162(h0, h1);
                pl[p2] = __nv_bfloat162(__float2bfloat16(v0 - __bfloat162float(h0)),
                                        __float2bfloat16(v1 - __bfloat162float(h1)));
            }
            uint32_t off = (uint32_t)rl * 128 + (uint32_t)colbase * 2 + j8 * 16;
            off ^= ((off >> 3) & 0x70);
            *(uint4*)(ahi + off) = *(uint4*)ph;
            *(uint4*)(alo + off) = *(uint4*)pl;
        }
        if (tail) {
            float4* hd = (float4*)(hlast + (size_t)tb * HH) + half * 8;
#pragma unroll
            for (int j = 0; j < 8; j++)
                hd[j] = make_float4(hv[4*j], hv[4*j+1], hv[4*j+2], hv[4*j+3]);
        }
    } else {
        float4* od = (float4*)(outp + (size_t)myrow * HH) + half * 8;
#pragma unroll
        for (int j = 0; j < 8; j++)
            od[j] = make_float4(hv[4*j], hv[4*j+1], hv[4*j+2], hv[4*j+3]);
        if (tail) {
            float4* hd = (float4*)(hlast + (size_t)tb * HH) + half * 8;
#pragma unroll
            for (int j = 0; j < 8; j++)
                hd[j] = make_float4(hv[4*j], hv[4*j+1], hv[4*j+2], hv[4*j+3]);
        }
    }
    __syncthreads();   // protect exchange buffers for any later reuse
}
#endif // HAS_TC

// ================================================================ fused kernel
// One CTA = 128 rows through BOTH layers. Layer-0: K=512 in 8 chunks via
// tcgen05 (3-term bf16 split). Epilogue-0 writes h_ln straight into the SMEM
// A tile; layer-1 GEMM reuses TMEM accumulators; epilogue-1 writes output.
__global__ void __launch_bounds__(256, 2)
qlstm_fused_kernel(const float* __restrict__ x,
                   const __nv_bfloat16* __restrict__ B0hi_g,
                   const __nv_bfloat16* __restrict__ B0lo_g,
                   const __nv_bfloat16* __restrict__ B1hi_g,
                   const __nv_bfloat16* __restrict__ B1lo_g,
                   const float* __restrict__ b0, const float* __restrict__ th0,
                   const float* __restrict__ g0, const float* __restrict__ be0,
                   const float* __restrict__ b1, const float* __restrict__ th1,
                   const float* __restrict__ g1, const float* __restrict__ be1,
                   float* __restrict__ out,
                   float* __restrict__ h0last, float* __restrict__ c0last,
                   float* __restrict__ h1last, float* __restrict__ c1last)
{
#ifdef HAS_TC
    constexpr int NC = 8;
    extern __shared__ __align__(1024) char smem[];
    const uint32_t sb = smem_u32(smem);
    const int tid = threadIdx.x, wid = tid >> 5, lane = tid & 31;
    const int half = wid >> 2;
    const int rl   = (wid & 3) * 32 + lane;     // local row 0..127
    const int row0 = blockIdx.x * 128;
    const int myrow = row0 + rl;

    float* fp   = (float*)(smem + OFF_MISC + 32);
    float* bt0  = fp;          // 192
    float* bt1  = fp + 192;    // 192
    float* gm0  = fp + 384;    // 64
    float* bet0 = fp + 448;
    float* gm1  = fp + 512;
    float* bet1 = fp + 576;
    float* ex0  = fp + 640;    // 128
    float* ex1  = fp + 768;    // 128

    if (tid < NG) {
        bt0[tid] = b0[64 + tid] + th0[64 + tid];
        bt1[tid] = b1[64 + tid] + th1[64 + tid];
    }
    if (tid >= 192 && tid < 256) {
        int i = tid - 192;
        gm0[i] = g0[i]; bet0[i] = be0[i];
        gm1[i] = g1[i]; bet1[i] = be1[i];
    }

    const uint32_t mb = sb + OFF_MISC + 8;
    if (wid == 0) {
        asm volatile("tcgen05.alloc.cta_group::1.sync.aligned.shared::cta.b32 [%0], %1;"
                     :: "r"(sb + OFF_MISC), "r"(256u) : "memory");
        asm volatile("tcgen05.relinquish_alloc_permit.cta_group::1.sync.aligned;");
    }
    if (tid == 0) {
        asm volatile("mbarrier.init.shared.b64 [%0], %1;" :: "r"(mb), "r"(1u) : "memory");
    }
    __syncthreads();
    uint32_t tmem;
    asm volatile("ld.shared.b32 %0, [%1];" : "=r"(tmem) : "r"(sb + OFF_MISC));

    char* ah = smem + OFF_A_HI;
    char* al = smem + OFF_A_LO;

    // ---------------- layer-0 K-chunk loop (single buffer) ----------------
    for (int c = 0; c < NC; c++) {
        if (c > 0) mbar_wait(mb, (c - 1) & 1);

        {   // A: fp32 -> bf16 hi/lo, SW128-swizzled STS (8 float4 / thread)
#pragma unroll
            for (int j = 0; j < 8; j++) {
                int idx = tid + j * 256;
                int r = idx >> 4, s = idx & 15;
                float4 v = *(const float4*)(x + (size_t)(row0 + r) * DDIM + c * 64 + s * 4);
                __nv_bfloat16 hx = __float2bfloat16(v.x);
                __nv_bfloat16 hy = __float2bfloat16(v.y);
                __nv_bfloat16 hz = __float2bfloat16(v.z);
                __nv_bfloat16 hw = __float2bfloat16(v.w);
                __nv_bfloat16 lx = __float2bfloat16(v.x - __bfloat162float(hx));
                __nv_bfloat16 ly = __float2bfloat16(v.y - __bfloat162float(hy));
                __nv_bfloat16 lz = __float2bfloat16(v.z - __bfloat162float(hz));
                __nv_bfloat16 lw = __float2bfloat16(v.w - __bfloat162float(hw));
                uint32_t off = (uint32_t)r * 128 + (uint32_t)s * 8;
                off ^= ((off >> 3) & 0x70);
                *(__nv_bfloat162*)(ah + off)     = __nv_bfloat162(hx, hy);
                *(__nv_bfloat162*)(ah + off + 4) = __nv_bfloat162(hz, hw);
                *(__nv_bfloat162*)(al + off)     = __nv_bfloat162(lx, ly);
                *(__nv_bfloat162*)(al + off + 4) = __nv_bfloat162(lz, lw);
            }
        }
        {   // B: pre-swizzled raw copy (6 float4 / thread per buffer)
            const float4* bh = (const float4*)(B0hi_g + (size_t)c * (NG * 64));
            const float4* bl = (const float4*)(B0lo_g + (size_t)c * (NG * 64));
            float4* sh = (float4*)(smem + OFF_B_HI);
            float4* sl = (float4*)(smem + OFF_B_LO);
#pragma unroll
            for (int j = 0; j < 6; j++) {
                int idx = tid + j * 256;
                sh[idx] = bh[idx];
                sl[idx] = bl[idx];
            }
        }
        __syncthreads();

        if (wid == 0 && elect1()) {
            asm volatile("fence.proxy.async.shared::cta;" ::: "memory");
            uint64_t aH = sdesc(sb + OFF_A_HI);
            uint64_t aL = sdesc(sb + OFF_A_LO);
            uint64_t bH = sdesc(sb + OFF_B_HI);
            uint64_t bL = sdesc(sb + OFF_B_LO);
#pragma unroll
            for (int ks = 0; ks < 4; ks++)
                mma_bf16_ss(tmem, aH + ks * 2, bH + ks * 2, IDESC, !(c == 0 && ks == 0));
#pragma unroll
            for (int ks = 0; ks < 4; ks++)
                mma_bf16_ss(tmem, aH + ks * 2, bL + ks * 2, IDESC, true);
#pragma unroll
            for (int ks = 0; ks < 4; ks++)
                mma_bf16_ss(tmem, aL + ks * 2, bH + ks * 2, IDESC, true);
            asm volatile(
                "tcgen05.commit.cta_group::1.mbarrier::arrive::one.shared::cluster.b64 [%0];"
                :: "r"(mb) : "memory");
        }
        if (c + 1 < NC) __syncthreads();
    }

    mbar_wait(mb, (NC - 1) & 1);
    asm volatile("tcgen05.fence::after_thread_sync;" ::: "memory");

    // B1 into the (now idle) B buffer, overlapped with epilogue-0 compute
    {
        const float4* bh = (const float4*)B1hi_g;
        const float4* bl = (const float4*)B1lo_g;
        float4* sh = (float4*)(smem + OFF_B_HI);
        float4* sl = (float4*)(smem + OFF_B_LO);
#pragma unroll
        for (int j = 0; j < 6; j++) {
            int idx = tid + j * 256;
            sh[idx] = bh[idx];
            sl[idx] = bl[idx];
        }
    }

    // ---------------- epilogue 0 (writes A tile in SMEM) ----------------
    epilogue_half<true>(tmem, bt0, gm0, bet0, ex0, ex1, ah, al,
                        nullptr, h0last, c0last, half, rl, myrow);

    // TMEM accumulator reuse: all LDTMs done -> fence -> bar -> MMA overwrites
    asm volatile("tcgen05.fence::before_thread_sync;" ::: "memory");
    __syncthreads();

    // ---------------- layer-1 GEMM (K=64, reuse TMEM cols 0-191) ----------
    if (wid == 0 && elect1()) {
        asm volatile("tcgen05.fence::after_thread_sync;" ::: "memory");
        asm volatile("fence.proxy.async.shared::cta;" ::: "memory");
        uint64_t aH = sdesc(sb + OFF_A_HI);
        uint64_t aL = sdesc(sb + OFF_A_LO);
        uint64_t bH = sdesc(sb + OFF_B_HI);
        uint64_t bL = sdesc(sb + OFF_B_LO);
#pragma unroll
        for (int ks = 0; ks < 4; ks++)
            mma_bf16_ss(tmem, aH + ks * 2, bH + ks * 2, IDESC, ks != 0);
#pragma unroll
        for (int ks = 0; ks < 4; ks++)
            mma_bf16_ss(tmem, aH + ks * 2, bL + ks * 2, IDESC, true);
#pragma unroll
        for (int ks = 0; ks < 4; ks++)
            mma_bf16_ss(tmem, aL + ks * 2, bH + ks * 2, IDESC, true);
        asm volatile(
            "tcgen05.commit.cta_group::1.mbarrier::arrive::one.shared::cluster.b64 [%0];"
            :: "r"(mb) : "memory");
    }
    mbar_wait(mb, NC & 1);      // 9th completion -> parity 0
    asm volatile("tcgen05.fence::after_thread_sync;" ::: "memory");

    // ---------------- epilogue 1 (writes final output) ----------------
    epilogue_half<false>(tmem, bt1, gm1, bet1, ex0, ex1, nullptr, nullptr,
                         out, h1last, c1last, half, rl, myrow);

    asm volatile("tcgen05.fence::before_thread_sync;" ::: "memory");
    __syncthreads();
    if (wid == 0) {
        asm volatile("tcgen05.dealloc.cta_group::1.sync.aligned.b32 %0, %1;"
                     :: "r"(tmem), "r"(256u));
    }
#endif // HAS_TC
}

// ================================================================ scalar kernel
// Fallback for non-arch-specific targets (empty on sm_103a-specific SASS).
__device__ __forceinline__ float sigmoidf_(float x) {
    return 1.0f / (1.0f + expf(-x));
}

template <int K>
__global__ __launch_bounds__(256)
void qlstm_layer_kernel(const float* __restrict__ x,
                        const float* __restrict__ WT,
                        const float* __restrict__ bvec,
                        const float* __restrict__ thvec,
                        const float* __restrict__ gamma,
                        const float* __restrict__ beta,
                        float* __restrict__ hln_out,
                        float* __restrict__ hlast,
                        float* __restrict__ clast)
{
#ifndef HAS_TC
    constexpr int BM = 32, BN = NG, BK = 16;
    __shared__ float xs[BK][BM];
    __shared__ __align__(16) float ws[BK][BN];
    __shared__ float zs[BM][BN];
    __shared__ float bt[BN];
    __shared__ float gmm[HH], bet[HH];

    const int tid  = threadIdx.x;
    const int row0 = blockIdx.x * BM;

    if (tid < NG) bt[tid] = bvec[64 + tid] + thvec[64 + tid];
    if (tid < HH) { gmm[tid] = gamma[tid]; bet[tid] = beta[tid]; }

    const int tc = tid & 15;
    const int tr = tid >> 4;

    float acc[2][12];
#pragma unroll
    for (int i = 0; i < 2; i++)
#pragma unroll
        for (int j = 0; j < 12; j++) acc[i][j] = 0.0f;

    for (int kt = 0; kt < K; kt += BK) {
        __syncthreads();
        if (tid < 128) {
            int r = tid >> 2, s = tid & 3;
            float4 v = *(const float4*)(x + (size_t)(row0 + r) * K + kt + s * 4);
            xs[s * 4 + 0][r] = v.x;
            xs[s * 4 + 1][r] = v.y;
            xs[s * 4 + 2][r] = v.z;
            xs[s * 4 + 3][r] = v.w;
        }
#pragma unroll
        for (int i = 0; i < 3; i++) {
            int f = tid + i * 256;
            int k = f / 48, n4 = f % 48;
            float4 v = *(const float4*)(WT + (size_t)(kt + k) * BN + n4 * 4);
            *(float4*)&ws[k][n4 * 4] = v;
        }
        __syncthreads();

#pragma unroll
        for (int k = 0; k < BK; k++) {
            float a0 = xs[k][2 * tr];
            float a1 = xs[k][2 * tr + 1];
            float bv[12];
#pragma unroll
            for (int j = 0; j < 3; j++) {
                float4 w4 = *(const float4*)&ws[k][tc * 12 + j * 4];
                bv[j * 4 + 0] = w4.x; bv[j * 4 + 1] = w4.y;
                bv[j * 4 + 2] = w4.z; bv[j * 4 + 3] = w4.w;
            }
#pragma unroll
            for (int j = 0; j < 12; j++) {
                acc[0][j] = fmaf(a0, bv[j], acc[0][j]);
                acc[1][j] = fmaf(a1, bv[j], acc[1][j]);
            }
        }
    }

    __syncthreads();
#pragma unroll
    for (int i = 0; i < 2; i++)
#pragma unroll
        for (int j = 0; j < 12; j++)
            zs[2 * tr + i][tc * 12 + j] = acc[i][j];
    __syncthreads();

    const int warp = tid >> 5, lane = tid & 31;
    const int n0 = 2 * lane, n1 = 2 * lane + 1;

#pragma unroll
    for (int rr = 0; rr < 4; rr++) {
        int r    = warp * 4 + rr;
        int grow = row0 + r;

        float sg[3][2];
#pragma unroll
        for (int g = 0; g < 3; g++) {
            float z0 = zs[r][g * 64 + n0] + bt[g * 64 + n0];
            float z1 = zs[r][g * 64 + n1] + bt[g * 64 + n1];
            float c0 = cosf(z0);
            float c1 = cosf(z1);
            float incl = c0 * c1;
#pragma unroll
            for (int off = 1; off < 32; off <<= 1) {
                float t = __shfl_up_sync(0xffffffffu, incl, off);
                if (lane >= off) incl *= t;
            }
            float excl = __shfl_up_sync(0xffffffffu, incl, 1);
            if (lane == 0) excl = 1.0f;
            float q0 = excl * c0;
            float q1 = incl;
            sg[g][0] = sigmoidf_(q0);
            sg[g][1] = sigmoidf_(q1);
        }
        float cv0 = sg[0][0] * tanhf(sg[1][0]);
        float cv1 = sg[0][1] * tanhf(sg[1][1]);
        float h0v = sg[2][0] * tanhf(cv0);
        float h1v = sg[2][1] * tanhf(cv1);

        float s = h0v + h1v;
#pragma unroll
        for (int off = 16; off; off >>= 1) s += __shfl_xor_sync(0xffffffffu, s, off);
        float mu = s * (1.0f / 64.0f);
        float d0 = h0v - mu, d1 = h1v - mu;
        float ssq = d0 * d0 + d1 * d1;
#pragma unroll
        for (int off = 16; off; off >>= 1) ssq += __shfl_xor_sync(0xffffffffu, ssq, off);
        float rinv = rsqrtf(ssq * (1.0f / 64.0f) + EPSV);

        float o0 = d0 * rinv * gmm[n0] + bet[n0];
        float o1 = d1 * rinv * gmm[n1] + bet[n1];

        *(float2*)(hln_out + (size_t)grow * HH + n0) = make_float2(o0, o1);

        if (grow >= NROWS - BB) {
            int bi = grow - (NROWS - BB);
            *(float2*)(hlast + (size_t)bi * HH + n0) = make_float2(o0, o1);
            *(float2*)(clast + (size_t)bi * HH + n0) = make_float2(cv0, cv1);
        }
    }
#endif // !HAS_TC
}

// ================================================================ launch
extern "C" void kernel_launch(void* const* d_in, const int* in_sizes, int n_in,
                              void* d_out, int out_size) {
    const float* inputs = (const float*)d_in[0];
    const float* W0  = (const float*)d_in[1];
    const float* b0  = (const float*)d_in[2];
    const float* th0 = (const float*)d_in[3];
    const float* g0  = (const float*)d_in[4];
    const float* be0 = (const float*)d_in[5];
    const float* W1  = (const float*)d_in[6];
    const float* b1  = (const float*)d_in[7];
    const float* th1 = (const float*)d_in[8];
    const float* g1  = (const float*)d_in[9];
    const float* be1 = (const float*)d_in[10];

    float* out = (float*)d_out;
    const size_t out_main = (size_t)NROWS * HH;
    float* h0last = out + out_main;
    float* c0last = h0last + BB * HH;
    float* h1last = c0last + BB * HH;
    float* c1last = h1last + BB * HH;

    float *h0p, *wt0p, *wt1p;
    __nv_bfloat16 *b0hi, *b0lo, *b1hi, *b1lo;
    cudaGetSymbolAddress((void**)&h0p,  g_h0);
    cudaGetSymbolAddress((void**)&wt0p, g_WT0);
    cudaGetSymbolAddress((void**)&wt1p, g_WT1);
    cudaGetSymbolAddress((void**)&b0hi, g_B0hi);
    cudaGetSymbolAddress((void**)&b0lo, g_B0lo);
    cudaGetSymbolAddress((void**)&b1hi, g_B1hi);
    cudaGetSymbolAddress((void**)&b1lo, g_B1lo);

    cudaFuncSetAttribute((const void*)qlstm_fused_kernel,
                         cudaFuncAttributeMaxDynamicSharedMemorySize, SMEM_TOTAL);

    prep_w_kernel<<<(8 * NG * 64 + 255) / 256, 256>>>(W0, W1);
    transpose_w_kernel<<<(DDIM * NG + 255) / 256, 256>>>(W0, W1);

    // Fused tensor-core path (arch-specific targets; no-op otherwise)
    qlstm_fused_kernel<<<NROWS / 128, 256, SMEM_TOTAL>>>(
        inputs, b0hi, b0lo, b1hi, b1lo,
        b0, th0, g0, be0, b1, th1, g1, be1,
        out, h0last, c0last, h1last, c1last);

    // Scalar fallback path (non-arch-specific targets; no-ops otherwise)
    qlstm_layer_kernel<DDIM><<<NROWS / 32, 256>>>(
        inputs, wt0p, b0, th0, g0, be0, h0p, h0last, c0last);
    qlstm_layer_kernel<HH><<<NROWS / 32, 256>>>(
        h0p, wt1p, b1, th1, g1, be1, out, h1last, c1last);
}

// round 6
// speedup vs baseline: 11.9535x; 1.1442x over previous
#include <cuda_runtime.h>
#include <cuda_bf16.h>
#include <math.h>
#include <stdint.h>

// ---------------------------------------------------------------- constants
#define TT     512
#define BB     128
#define DDIM   512
#define HH     64
#define NROWS  (TT * BB)          // 65536 independent (t,b) rows
#define NG     192                // 3 gates (i, g, o) x 64 qubits
#define EPSV   1e-5f

// Arch-specific feature gate: tcgen05 exists only on sm_10xa targets.
#if defined(__CUDA_ARCH__) && (defined(__CUDA_ARCH_FEAT_SM103_ALL) || \
    defined(__CUDA_ARCH_FEAT_SM100_ALL) || defined(__CUDA_ARCH_SPECIFIC__))
#define HAS_TC 1
#endif

// dynamic SMEM layout (tensor path), single-buffered; 2 CTAs/SM (TMEM-capped)
#define OFF_A_HI   0              // 16384  (128 rows x 64 bf16, SW128)
#define OFF_A_LO   16384          // 16384
#define OFF_B_HI   32768          // 24576  (192 rows x 64 bf16, SW128)
#define OFF_B_LO   57344          // 24576
#define OFF_MISC   81920          // tmem ptr, mbarrier, params, exchange bufs
#define SMEM_TOTAL 86016

// idesc: kind::f16, bf16 x bf16 -> f32, M=128, N=192
#define IDESC ((1u << 4) | (1u << 7) | (1u << 10) | ((NG / 8) << 17) | ((128 / 16) << 24))

// ---------------------------------------------------------------- scratch
__device__ __nv_bfloat16  g_B0hi[8 * NG * 64];   // W0: 8 K-chunks, SW128 swizzled
__device__ __nv_bfloat16  g_B0lo[8 * NG * 64];
__device__ __nv_bfloat16  g_B1hi[NG * 64];       // W1: 1 K-chunk
__device__ __nv_bfloat16  g_B1lo[NG * 64];

// ================================================================ prolog
// Split W (gates 1..3, first K cols) into bf16 hi/lo, B-operand SW128 layout.
__global__ void prep_w_kernel(const float* __restrict__ W0,
                              const float* __restrict__ W1) {
#ifdef HAS_TC
    int idx = blockIdx.x * blockDim.x + threadIdx.x;
    if (idx < 8 * NG * 64) {
        int c   = idx / (NG * 64);
        int rem = idx % (NG * 64);
        int n   = rem / 64, kl = rem % 64;
        float w = W0[(size_t)(64 + n) * (DDIM + HH) + c * 64 + kl];
        __nv_bfloat16 hi = __float2bfloat16(w);
        __nv_bfloat16 lo = __float2bfloat16(w - __bfloat162float(hi));
        uint32_t boff = ((uint32_t)(n >> 3)) * 1024 + ((uint32_t)(n & 7)) * 128 + kl * 2;
        boff ^= ((boff >> 3) & 0x70);
        g_B0hi[(size_t)c * (NG * 64) + boff / 2] = hi;
        g_B0lo[(size_t)c * (NG * 64) + boff / 2] = lo;
    }
    if (idx < NG * 64) {
        int n = idx / 64, kl = idx % 64;
        float w = W1[(size_t)(64 + n) * (HH + HH) + kl];
        __nv_bfloat16 hi = __float2bfloat16(w);
        __nv_bfloat16 lo = __float2bfloat16(w - __bfloat162float(hi));
        uint32_t boff = ((uint32_t)(n >> 3)) * 1024 + ((uint32_t)(n & 7)) * 128 + kl * 2;
        boff ^= ((boff >> 3) & 0x70);
        g_B1hi[boff / 2] = hi;
        g_B1lo[boff / 2] = lo;
    }
#endif
}

// ================================================================ PTX helpers
#ifdef HAS_TC
static __device__ __forceinline__ uint32_t smem_u32(const void* p) {
    uint32_t a;
    asm("{ .reg .u64 t; cvta.to.shared.u64 t, %1; cvt.u32.u64 %0, t; }"
        : "=r"(a) : "l"(p));
    return a;
}
static __device__ __forceinline__ uint32_t elect1() {
    uint32_t p;
    asm volatile("{\n .reg .pred p;\n elect.sync _|p, 0xFFFFFFFF;\n selp.b32 %0,1,0,p;\n}"
                 : "=r"(p));
    return p;
}
static __device__ __forceinline__ uint64_t sdesc(uint32_t addr) {
    return (2ull << 61) | (1ull << 46) | (64ull << 32) | (1ull << 16)
         | ((uint64_t)(addr >> 4) & 0x3FFF);
}
static __device__ __forceinline__ void mma_bf16_ss(uint32_t d, uint64_t ad, uint64_t bd,
                                                   uint32_t idesc, bool accum) {
    uint32_t en = accum ? 1u : 0u;
    asm volatile(
        "{\n\t"
        ".reg .pred p;\n\t"
        "setp.ne.u32 p, %5, 0;\n\t"
        "tcgen05.mma.cta_group::1.kind::f16 [%0], %1, %2, %3, {%4, %4, %4, %4}, p;\n\t"
        "}"
        :: "r"(d), "l"(ad), "l"(bd), "r"(idesc), "r"(0u), "r"(en)
        : "memory");
}
static __device__ __forceinline__ void mbar_wait(uint32_t mbar, uint32_t parity) {
    uint32_t done;
    asm volatile(
        "{\n .reg .pred p;\n"
        " mbarrier.try_wait.parity.acquire.cta.shared::cta.b64 p, [%1], %2;\n"
        " selp.b32 %0, 1, 0, p;\n}"
        : "=r"(done) : "r"(mbar), "r"(parity) : "memory");
    if (!done) {
        asm volatile(
            "{\n .reg .pred P1;\n"
            "WL%=:\n"
            " mbarrier.try_wait.parity.acquire.cta.shared::cta.b64 P1, [%0], %1, 0x989680;\n"
            " @P1 bra.uni WD%=;\n"
            " bra.uni WL%=;\n"
            "WD%=:\n}"
            :: "r"(mbar), "r"(parity) : "memory");
    }
}
#define TC_WAIT_LD() asm volatile("tcgen05.wait::ld.sync.aligned;" ::: "memory")
#define LDTM_X32(r, addr)                                              \
    asm volatile(                                                       \
        "tcgen05.ld.sync.aligned.32x32b.x32.b32 "                       \
        "{%0, %1, %2, %3, %4, %5, %6, %7, "                             \
        " %8, %9, %10, %11, %12, %13, %14, %15, "                       \
        " %16, %17, %18, %19, %20, %21, %22, %23, "                     \
        " %24, %25, %26, %27, %28, %29, %30, %31}, [%32];"              \
        : "=r"((r)[0]),  "=r"((r)[1]),  "=r"((r)[2]),  "=r"((r)[3]),    \
          "=r"((r)[4]),  "=r"((r)[5]),  "=r"((r)[6]),  "=r"((r)[7]),    \
          "=r"((r)[8]),  "=r"((r)[9]),  "=r"((r)[10]), "=r"((r)[11]),   \
          "=r"((r)[12]), "=r"((r)[13]), "=r"((r)[14]), "=r"((r)[15]),   \
          "=r"((r)[16]), "=r"((r)[17]), "=r"((r)[18]), "=r"((r)[19]),   \
          "=r"((r)[20]), "=r"((r)[21]), "=r"((r)[22]), "=r"((r)[23]),   \
          "=r"((r)[24]), "=r"((r)[25]), "=r"((r)[26]), "=r"((r)[27]),   \
          "=r"((r)[28]), "=r"((r)[29]), "=r"((r)[30]), "=r"((r)[31])    \
        : "r"(addr))

static __device__ __forceinline__ float frcp(float x) {
    float y; asm("rcp.approx.f32 %0, %1;" : "=f"(y) : "f"(x)); return y;
}
// sigmoid(q), |q| <= 1: odd Taylor/poly deg-11, err ~2e-7, FMA-only (0 MUFU)
static __device__ __forceinline__ float psig(float q) {
    float u = q * q;
    float p = fmaf(u, -2.1638741e-6f, 2.1358436e-5f);
    p = fmaf(u, p, -2.1081349e-4f);
    p = fmaf(u, p,  2.0833333e-3f);
    p = fmaf(u, p, -2.0833333e-2f);
    p = fmaf(u, p,  0.25f);
    return fmaf(q, p, 0.5f);
}
// tanh(x), 0 <= x <= 0.75: Pade(7,6), err < 1e-8, 1 MUFU rcp + FMAs
static __device__ __forceinline__ float ptanh(float x) {
    float u = x * x;
    float n = fmaf(u + 378.0f, u, 17325.0f);
    n = fmaf(n, u, 135135.0f);
    float d = fmaf(28.0f, u, 3150.0f);
    d = fmaf(d, u, 62370.0f);
    d = fmaf(d, u, 135135.0f);
    return x * n * frcp(d);
}

// ---------------------------------------------------------------- epilogue half
// Warp pair (w, w+4) shares rows (w&3)*32+lane; each half owns 32 gate columns.
// L0: write h_ln as bf16 hi/lo into SMEM A tile; else write fp32 to global out.
template <bool L0>
static __device__ __forceinline__ void epilogue_half(
    uint32_t tmem, const float* __restrict__ bt,
    const float* __restrict__ gm, const float* __restrict__ bet,
    volatile float* ex0, volatile float* ex1,
    char* ahi, char* alo, float* __restrict__ outp,
    float* __restrict__ hlast, float* __restrict__ clast,
    int half, int rl, int myrow)
{
    float hv[32], cs[32];
    uint32_t* ru = (uint32_t*)cs;
    const int colbase = half * 32;
    const bool tail = (myrow >= NROWS - BB);
    const int tb = myrow - (NROWS - BB);

#pragma unroll
    for (int g = 0; g < 3; g++) {
        LDTM_X32(ru, tmem + g * 64 + colbase);
        TC_WAIT_LD();
#pragma unroll
        for (int j = 0; j < 32; j++)
            cs[j] = __cosf(__uint_as_float(ru[j]) + bt[g * 64 + colbase + j]);
        // local inclusive multiply-scan of 32: 4 chains of 8, then group prefix
#pragma unroll
        for (int g8 = 0; g8 < 4; g8++)
#pragma unroll
            for (int j = 1; j < 8; j++)
                cs[g8 * 8 + j] *= cs[g8 * 8 + j - 1];
        float pref = 1.0f;
#pragma unroll
        for (int g8 = 0; g8 < 4; g8++) {
            float tot = cs[g8 * 8 + 7];
#pragma unroll
            for (int j = 0; j < 8; j++) cs[g8 * 8 + j] *= pref;
            pref *= tot;
        }
        // cross-half prefix: low publishes its total, high multiplies it in
        if (half == 0) ex0[rl] = pref;
        __syncthreads();
        if (half == 1) {
            float p = ex0[rl];
#pragma unroll
            for (int j = 0; j < 32; j++) cs[j] *= p;
        }
        __syncthreads();

        if (g == 0) {
#pragma unroll
            for (int j = 0; j < 32; j++) hv[j] = psig(cs[j]);
        } else if (g == 1) {
#pragma unroll
            for (int j = 0; j < 32; j++) hv[j] *= ptanh(psig(cs[j]));   // c
            if (tail) {
                float4* cd = (float4*)(clast + (size_t)tb * HH) + half * 8;
#pragma unroll
                for (int j = 0; j < 8; j++)
                    cd[j] = make_float4(hv[4*j], hv[4*j+1], hv[4*j+2], hv[4*j+3]);
            }
        } else {
#pragma unroll
            for (int j = 0; j < 32; j++) hv[j] = psig(cs[j]) * ptanh(hv[j]);  // h
        }
    }

    // layernorm across the pair
    float s = 0.0f;
#pragma unroll
    for (int j = 0; j < 32; j++) s += hv[j];
    if (half == 0) ex0[rl] = s; else ex1[rl] = s;
    __syncthreads();
    float mu = (ex0[rl] + ex1[rl]) * (1.0f / 64.0f);
    float q = 0.0f;
#pragma unroll
    for (int j = 0; j < 32; j++) { float d = hv[j] - mu; q += d * d; }
    __syncthreads();
    if (half == 0) ex0[rl] = q; else ex1[rl] = q;
    __syncthreads();
    float rinv = rsqrtf((ex0[rl] + ex1[rl]) * (1.0f / 64.0f) + EPSV);
#pragma unroll
    for (int j = 0; j < 32; j++)
        hv[j] = (hv[j] - mu) * rinv * gm[colbase + j] + bet[colbase + j];

    if (L0) {
        // h_ln -> bf16 hi/lo into SMEM A tile (SW128, layer-1 operand)
#pragma unroll
        for (int j8 = 0; j8 < 4; j8++) {
            __nv_bfloat162 ph[4], pl[4];
#pragma unroll
            for (int p2 = 0; p2 < 4; p2++) {
                float v0 = hv[j8 * 8 + p2 * 2], v1 = hv[j8 * 8 + p2 * 2 + 1];
                __nv_bfloat16 h0 = __float2bfloat16(v0);
                __nv_bfloat16 h1 = __float2bfloat16(v1);
                ph[p2] = __nv_bfloat162(h0, h1);
                pl[p2] = __nv_bfloat162(__float2bfloat16(v0 - __bfloat162float(h0)),
                                        __float2bfloat16(v1 - __bfloat162float(h1)));
            }
            uint32_t off = (uint32_t)rl * 128 + (uint32_t)colbase * 2 + j8 * 16;
            off ^= ((off >> 3) & 0x70);
            *(uint4*)(ahi + off) = *(uint4*)ph;
            *(uint4*)(alo + off) = *(uint4*)pl;
        }
        if (tail) {
            float4* hd = (float4*)(hlast + (size_t)tb * HH) + half * 8;
#pragma unroll
            for (int j = 0; j < 8; j++)
                hd[j] = make_float4(hv[4*j], hv[4*j+1], hv[4*j+2], hv[4*j+3]);
        }
    } else {
        float4* od = (float4*)(outp + (size_t)myrow * HH) + half * 8;
#pragma unroll
        for (int j = 0; j < 8; j++)
            od[j] = make_float4(hv[4*j], hv[4*j+1], hv[4*j+2], hv[4*j+3]);
        if (tail) {
            float4* hd = (float4*)(hlast + (size_t)tb * HH) + half * 8;
#pragma unroll
            for (int j = 0; j < 8; j++)
                hd[j] = make_float4(hv[4*j], hv[4*j+1], hv[4*j+2], hv[4*j+3]);
        }
    }
    __syncthreads();   // protect exchange buffers for later reuse
}
#endif // HAS_TC

// ================================================================ fused kernel
// One CTA = 128 rows through BOTH layers.
// HAS_TC: tcgen05 bf16 3-term split GEMMs + TMEM-reuse + fused epilogues.
// else:   scalar smem-tiled fallback (correctness-only; never the fast path).
__global__ void __launch_bounds__(256, 2)
qlstm_fused_kernel(const float* __restrict__ x,
                   const float* __restrict__ W0raw,
                   const float* __restrict__ W1raw,
                   const __nv_bfloat16* __restrict__ B0hi_g,
                   const __nv_bfloat16* __restrict__ B0lo_g,
                   const __nv_bfloat16* __restrict__ B1hi_g,
                   const __nv_bfloat16* __restrict__ B1lo_g,
                   const float* __restrict__ b0, const float* __restrict__ th0,
                   const float* __restrict__ g0, const float* __restrict__ be0,
                   const float* __restrict__ b1, const float* __restrict__ th1,
                   const float* __restrict__ g1, const float* __restrict__ be1,
                   float* __restrict__ out,
                   float* __restrict__ h0last, float* __restrict__ c0last,
                   float* __restrict__ h1last, float* __restrict__ c1last)
{
    extern __shared__ __align__(1024) char smem[];
    const int tid = threadIdx.x, wid = tid >> 5, lane = tid & 31;
    const int half = wid >> 2;
    const int rl   = (wid & 3) * 32 + lane;     // local row 0..127
    const int row0 = blockIdx.x * 128;
    const int myrow = row0 + rl;

    float* fp   = (float*)(smem + OFF_MISC + 32);
    float* bt0  = fp;          // 192
    float* bt1  = fp + 192;    // 192
    float* gm0  = fp + 384;    // 64
    float* bet0 = fp + 448;
    float* gm1  = fp + 512;
    float* bet1 = fp + 576;
    float* ex0  = fp + 640;    // 128
    float* ex1  = fp + 768;    // 128

    if (tid < NG) {
        bt0[tid] = b0[64 + tid] + th0[64 + tid];
        bt1[tid] = b1[64 + tid] + th1[64 + tid];
    }
    if (tid >= 192 && tid < 256) {
        int i = tid - 192;
        gm0[i] = g0[i]; bet0[i] = be0[i];
        gm1[i] = g1[i]; bet1[i] = be1[i];
    }

#ifdef HAS_TC
    constexpr int NC = 8;
    const uint32_t sb = smem_u32(smem);
    const uint32_t mb = sb + OFF_MISC + 8;
    if (wid == 0) {
        asm volatile("tcgen05.alloc.cta_group::1.sync.aligned.shared::cta.b32 [%0], %1;"
                     :: "r"(sb + OFF_MISC), "r"(256u) : "memory");
        asm volatile("tcgen05.relinquish_alloc_permit.cta_group::1.sync.aligned;");
    }
    if (tid == 0) {
        asm volatile("mbarrier.init.shared.b64 [%0], %1;" :: "r"(mb), "r"(1u) : "memory");
    }
    __syncthreads();
    uint32_t tmem;
    asm volatile("ld.shared.b32 %0, [%1];" : "=r"(tmem) : "r"(sb + OFF_MISC));

    char* ah = smem + OFF_A_HI;
    char* al = smem + OFF_A_LO;

    // ---------------- layer-0 K-chunk loop (single buffer) ----------------
    for (int c = 0; c < NC; c++) {
        if (c > 0) mbar_wait(mb, (c - 1) & 1);

        {   // A: fp32 -> bf16 hi/lo, SW128-swizzled STS (8 float4 / thread)
#pragma unroll
            for (int j = 0; j < 8; j++) {
                int idx = tid + j * 256;
                int r = idx >> 4, s = idx & 15;
                float4 v = *(const float4*)(x + (size_t)(row0 + r) * DDIM + c * 64 + s * 4);
                __nv_bfloat16 hx = __float2bfloat16(v.x);
                __nv_bfloat16 hy = __float2bfloat16(v.y);
                __nv_bfloat16 hz = __float2bfloat16(v.z);
                __nv_bfloat16 hw = __float2bfloat16(v.w);
                __nv_bfloat16 lx = __float2bfloat16(v.x - __bfloat162float(hx));
                __nv_bfloat16 ly = __float2bfloat16(v.y - __bfloat162float(hy));
                __nv_bfloat16 lz = __float2bfloat16(v.z - __bfloat162float(hz));
                __nv_bfloat16 lw = __float2bfloat16(v.w - __bfloat162float(hw));
                uint32_t off = (uint32_t)r * 128 + (uint32_t)s * 8;
                off ^= ((off >> 3) & 0x70);
                *(__nv_bfloat162*)(ah + off)     = __nv_bfloat162(hx, hy);
                *(__nv_bfloat162*)(ah + off + 4) = __nv_bfloat162(hz, hw);
                *(__nv_bfloat162*)(al + off)     = __nv_bfloat162(lx, ly);
                *(__nv_bfloat162*)(al + off + 4) = __nv_bfloat162(lz, lw);
            }
        }
        {   // B: pre-swizzled raw copy (6 float4 / thread per buffer)
            const float4* bh = (const float4*)(B0hi_g + (size_t)c * (NG * 64));
            const float4* bl = (const float4*)(B0lo_g + (size_t)c * (NG * 64));
            float4* sh = (float4*)(smem + OFF_B_HI);
            float4* sl = (float4*)(smem + OFF_B_LO);
#pragma unroll
            for (int j = 0; j < 6; j++) {
                int idx = tid + j * 256;
                sh[idx] = bh[idx];
                sl[idx] = bl[idx];
            }
        }
        __syncthreads();

        if (wid == 0 && elect1()) {
            asm volatile("fence.proxy.async.shared::cta;" ::: "memory");
            uint64_t aH = sdesc(sb + OFF_A_HI);
            uint64_t aL = sdesc(sb + OFF_A_LO);
            uint64_t bH = sdesc(sb + OFF_B_HI);
            uint64_t bL = sdesc(sb + OFF_B_LO);
#pragma unroll
            for (int ks = 0; ks < 4; ks++)
                mma_bf16_ss(tmem, aH + ks * 2, bH + ks * 2, IDESC, !(c == 0 && ks == 0));
#pragma unroll
            for (int ks = 0; ks < 4; ks++)
                mma_bf16_ss(tmem, aH + ks * 2, bL + ks * 2, IDESC, true);
#pragma unroll
            for (int ks = 0; ks < 4; ks++)
                mma_bf16_ss(tmem, aL + ks * 2, bH + ks * 2, IDESC, true);
            asm volatile(
                "tcgen05.commit.cta_group::1.mbarrier::arrive::one.shared::cluster.b64 [%0];"
                :: "r"(mb) : "memory");
        }
        if (c + 1 < NC) __syncthreads();
    }

    mbar_wait(mb, (NC - 1) & 1);
    asm volatile("tcgen05.fence::after_thread_sync;" ::: "memory");

    // B1 into the (now idle) B buffer, overlapped with epilogue-0 compute
    {
        const float4* bh = (const float4*)B1hi_g;
        const float4* bl = (const float4*)B1lo_g;
        float4* sh = (float4*)(smem + OFF_B_HI);
        float4* sl = (float4*)(smem + OFF_B_LO);
#pragma unroll
        for (int j = 0; j < 6; j++) {
            int idx = tid + j * 256;
            sh[idx] = bh[idx];
            sl[idx] = bl[idx];
        }
    }

    // ---------------- epilogue 0 (writes A tile in SMEM) ----------------
    epilogue_half<true>(tmem, bt0, gm0, bet0, ex0, ex1, ah, al,
                        nullptr, h0last, c0last, half, rl, myrow);

    // TMEM accumulator reuse: all LDTMs done -> fence -> bar -> MMA overwrites
    asm volatile("tcgen05.fence::before_thread_sync;" ::: "memory");
    __syncthreads();

    // ---------------- layer-1 GEMM (K=64, reuse TMEM cols 0-191) ----------
    if (wid == 0 && elect1()) {
        asm volatile("tcgen05.fence::after_thread_sync;" ::: "memory");
        asm volatile("fence.proxy.async.shared::cta;" ::: "memory");
        uint64_t aH = sdesc(sb + OFF_A_HI);
        uint64_t aL = sdesc(sb + OFF_A_LO);
        uint64_t bH = sdesc(sb + OFF_B_HI);
        uint64_t bL = sdesc(sb + OFF_B_LO);
#pragma unroll
        for (int ks = 0; ks < 4; ks++)
            mma_bf16_ss(tmem, aH + ks * 2, bH + ks * 2, IDESC, ks != 0);
#pragma unroll
        for (int ks = 0; ks < 4; ks++)
            mma_bf16_ss(tmem, aH + ks * 2, bL + ks * 2, IDESC, true);
#pragma unroll
        for (int ks = 0; ks < 4; ks++)
            mma_bf16_ss(tmem, aL + ks * 2, bH + ks * 2, IDESC, true);
        asm volatile(
            "tcgen05.commit.cta_group::1.mbarrier::arrive::one.shared::cluster.b64 [%0];"
            :: "r"(mb) : "memory");
    }
    mbar_wait(mb, NC & 1);      // 9th completion -> parity 0
    asm volatile("tcgen05.fence::after_thread_sync;" ::: "memory");

    // ---------------- epilogue 1 (writes final output) ----------------
    epilogue_half<false>(tmem, bt1, gm1, bet1, ex0, ex1, nullptr, nullptr,
                         out, h1last, c1last, half, rl, myrow);

    asm volatile("tcgen05.fence::before_thread_sync;" ::: "memory");
    __syncthreads();
    if (wid == 0) {
        asm volatile("tcgen05.dealloc.cta_group::1.sync.aligned.b32 %0, %1;"
                     :: "r"(tmem), "r"(256u));
    }

#else  // ---------------- scalar fallback (correctness-only) ----------------
    float* xs = (float*)smem;                    // [128][64] fp32 x tile
    float* ws = (float*)(smem + 32768);          // [192][64] fp32 W tile
    const int colbase = half * 32;
    const bool tail = (myrow >= NROWS - BB);
    const int tb = myrow - (NROWS - BB);
    float z[96];
#pragma unroll
    for (int i = 0; i < 96; i++) z[i] = 0.0f;

    __syncthreads();
    // ---- layer 0 GEMM: K=512 in 8 chunks of 64 ----
    for (int kt = 0; kt < 8; kt++) {
        __syncthreads();
        for (int i = tid; i < 128 * 16; i += 256) {   // x tile (float4)
            int r = i >> 4, s = i & 15;
            *(float4*)&xs[r * 64 + s * 4] =
                *(const float4*)(x + (size_t)(row0 + r) * DDIM + kt * 64 + s * 4);
        }
        for (int i = tid; i < 192 * 16; i += 256) {   // W tile (float4)
            int n = i >> 4, s = i & 15;
            *(float4*)&ws[n * 64 + s * 4] =
                *(const float4*)(W0raw + (size_t)(64 + n) * (DDIM + HH) + kt * 64 + s * 4);
        }
        __syncthreads();
        for (int g = 0; g < 3; g++)
            for (int j = 0; j < 32; j++) {
                int n = g * 64 + colbase + j;
                float acc = z[g * 32 + j];
                for (int k = 0; k < 64; k++)
                    acc = fmaf(xs[rl * 64 + k], ws[n * 64 + k], acc);
                z[g * 32 + j] = acc;
            }
    }

    for (int layer = 0; layer < 2; layer++) {
        const float* bt  = layer ? bt1  : bt0;
        const float* gm  = layer ? gm1  : gm0;
        const float* bet = layer ? bet1 : bet0;
        float* hl = layer ? h1last : h0last;
        float* cl = layer ? c1last : c0last;
        float hv[32];
        // epilogue (same warp-pair split as TC path, precise math)
        for (int g = 0; g < 3; g++) {
            float cs[32];
            for (int j = 0; j < 32; j++)
                cs[j] = cosf(z[g * 32 + j] + bt[g * 64 + colbase + j]);
            for (int j = 1; j < 32; j++) cs[j] *= cs[j - 1];
            if (half == 0) ex0[rl] = cs[31];
            __syncthreads();
            if (half == 1) { float p = ex0[rl]; for (int j = 0; j < 32; j++) cs[j] *= p; }
            __syncthreads();
            if (g == 0)      for (int j = 0; j < 32; j++) hv[j] = 1.0f / (1.0f + expf(-cs[j]));
            else if (g == 1) {
                for (int j = 0; j < 32; j++) hv[j] *= tanhf(1.0f / (1.0f + expf(-cs[j])));
                if (tail) for (int j = 0; j < 32; j++) cl[(size_t)tb * HH + colbase + j] = hv[j];
            } else           for (int j = 0; j < 32; j++) hv[j] = (1.0f / (1.0f + expf(-cs[j]))) * tanhf(hv[j]);
        }
        float s = 0.0f;
        for (int j = 0; j < 32; j++) s += hv[j];
        if (half == 0) ex0[rl] = s; else ex1[rl] = s;
        __syncthreads();
        float mu = (ex0[rl] + ex1[rl]) * (1.0f / 64.0f);
        float q = 0.0f;
        for (int j = 0; j < 32; j++) { float d = hv[j] - mu; q += d * d; }
        __syncthreads();
        if (half == 0) ex0[rl] = q; else ex1[rl] = q;
        __syncthreads();
        float rinv = rsqrtf((ex0[rl] + ex1[rl]) * (1.0f / 64.0f) + EPSV);
        for (int j = 0; j < 32; j++)
            hv[j] = (hv[j] - mu) * rinv * gm[colbase + j] + bet[colbase + j];
        __syncthreads();

        if (layer == 0) {
            // stage h_ln in xs, then layer-1 GEMM (K=64)
            for (int j = 0; j < 32; j++) xs[rl * 64 + colbase + j] = hv[j];
            __syncthreads();
            for (int i = tid; i < 192 * 16; i += 256) {
                int n = i >> 4, sdx = i & 15;
                *(float4*)&ws[n * 64 + sdx * 4] =
                    *(const float4*)(W1raw + (size_t)(64 + n) * (HH + HH) + sdx * 4);
            }
            __syncthreads();
            for (int g = 0; g < 3; g++)
                for (int j = 0; j < 32; j++) {
                    int n = g * 64 + colbase + j;
                    float acc = 0.0f;
                    for (int k = 0; k < 64; k++)
                        acc = fmaf(xs[rl * 64 + k], ws[n * 64 + k], acc);
                    z[g * 32 + j] = acc;
                }
        } else {
            for (int j = 0; j < 32; j++) out[(size_t)myrow * HH + colbase + j] = hv[j];
            if (tail) for (int j = 0; j < 32; j++) hl[(size_t)tb * HH + colbase + j] = hv[j];
        }
        if (layer == 0 && tail)
            for (int j = 0; j < 32; j++) hl[(size_t)tb * HH + colbase + j] = hv[j];
        __syncthreads();
    }
#endif // HAS_TC
}

// ================================================================ launch
extern "C" void kernel_launch(void* const* d_in, const int* in_sizes, int n_in,
                              void* d_out, int out_size) {
    const float* inputs = (const float*)d_in[0];
    const float* W0  = (const float*)d_in[1];
    const float* b0  = (const float*)d_in[2];
    const float* th0 = (const float*)d_in[3];
    const float* g0  = (const float*)d_in[4];
    const float* be0 = (const float*)d_in[5];
    const float* W1  = (const float*)d_in[6];
    const float* b1  = (const float*)d_in[7];
    const float* th1 = (const float*)d_in[8];
    const float* g1  = (const float*)d_in[9];
    const float* be1 = (const float*)d_in[10];

    float* out = (float*)d_out;
    const size_t out_main = (size_t)NROWS * HH;
    float* h0last = out + out_main;
    float* c0last = h0last + BB * HH;
    float* h1last = c0last + BB * HH;
    float* c1last = h1last + BB * HH;

    __nv_bfloat16 *b0hi, *b0lo, *b1hi, *b1lo;
    cudaGetSymbolAddress((void**)&b0hi, g_B0hi);
    cudaGetSymbolAddress((void**)&b0lo, g_B0lo);
    cudaGetSymbolAddress((void**)&b1hi, g_B1hi);
    cudaGetSymbolAddress((void**)&b1lo, g_B1lo);

    cudaFuncSetAttribute((const void*)qlstm_fused_kernel,
                         cudaFuncAttributeMaxDynamicSharedMemorySize, SMEM_TOTAL);

    prep_w_kernel<<<(8 * NG * 64 + 255) / 256, 256>>>(W0, W1);

    qlstm_fused_kernel<<<NROWS / 128, 256, SMEM_TOTAL>>>(
        inputs, W0, W1, b0hi, b0lo, b1hi, b1lo,
        b0, th0, g0, be0, b1, th1, g1, be1,
        out, h0last, c0last, h1last, c1last);
}